// round 1
// baseline (speedup 1.0000x reference)
#include <cuda_runtime.h>
#include <math.h>

// Problem constants
#define Bb     4
#define Tt     2048
#define DIMd   512
#define NHEAD  8
#define DHEAD  64
#define MLPD   2048
#define ADIM   256
#define NTOK   (Bb * Tt)          // 8192 tokens
#define MODC   (6 * DIMd)         // 3072 modulation cols

// ---------------------------------------------------------------------------
// Scratch (static device globals; allocation-free per harness rules)
// ---------------------------------------------------------------------------
__device__ float g_silu[NTOK * ADIM];            //  8.4 MB
__device__ float g_mod [(size_t)NTOK * MODC];    // 100.7 MB
__device__ float g_h   [NTOK * DIMd];            // 16.8 MB
__device__ float g_qkv [NTOK * 3 * DIMd];        // 50.3 MB
__device__ float g_attn[NTOK * DIMd];            // 16.8 MB
__device__ float g_x1  [NTOK * DIMd];            // 16.8 MB
__device__ float g_mlp [NTOK * MLPD];            // 67.1 MB

// ---------------------------------------------------------------------------
// SiLU elementwise
// ---------------------------------------------------------------------------
__global__ void silu_kernel(const float* __restrict__ a, float* __restrict__ out, int n)
{
    int i = blockIdx.x * blockDim.x + threadIdx.x;
    if (i < n) {
        float v = a[i];
        out[i] = v / (1.0f + __expf(-v));
    }
}

// ---------------------------------------------------------------------------
// Fused LayerNorm + AdaLN modulation: out = LN(x)*(1+scale)+shift
// One block per token, 128 threads, 4 elems/thread.
// ---------------------------------------------------------------------------
__global__ void lnmod_kernel(const float* __restrict__ x,
                             const float* __restrict__ mod,
                             int shift_off, int scale_off,
                             float* __restrict__ out)
{
    int row = blockIdx.x;
    int t   = threadIdx.x;
    const float* xr = x + (size_t)row * DIMd;

    float v[4];
    float s1 = 0.f, s2 = 0.f;
#pragma unroll
    for (int j = 0; j < 4; j++) {
        float z = xr[t + j * 128];
        v[j] = z; s1 += z; s2 += z * z;
    }
#pragma unroll
    for (int off = 16; off; off >>= 1) {
        s1 += __shfl_xor_sync(0xffffffffu, s1, off);
        s2 += __shfl_xor_sync(0xffffffffu, s2, off);
    }
    __shared__ float r1[4], r2[4];
    int w = t >> 5;
    if ((t & 31) == 0) { r1[w] = s1; r2[w] = s2; }
    __syncthreads();
    s1 = r1[0] + r1[1] + r1[2] + r1[3];
    s2 = r2[0] + r2[1] + r2[2] + r2[3];

    float mu   = s1 * (1.0f / DIMd);
    float var  = s2 * (1.0f / DIMd) - mu * mu;
    float rstd = rsqrtf(var + 1e-5f);

    const float* mrow = mod + (size_t)row * MODC;
    float* orow = out + (size_t)row * DIMd;
#pragma unroll
    for (int j = 0; j < 4; j++) {
        int c = t + j * 128;
        float sc = mrow[scale_off + c];
        float sh = mrow[shift_off + c];
        orow[c] = (v[j] - mu) * rstd * (1.0f + sc) + sh;
    }
}

// ---------------------------------------------------------------------------
// Tiled SGEMM: C[M,N] = A[M,K] @ B[N,K]^T (+bias) (+epilogue)
// BM=BN=128, BK=8, 256 threads, 8x8 microtile.
// EPI: 0 = bias only, 1 = exact GELU(acc+bias), 2 = res + gate*(acc+bias)
// gate has row stride MODC with column offset gate_off; res has N cols.
// ---------------------------------------------------------------------------
#define BM 128
#define BN 128
#define BK 8

__device__ __forceinline__ float gelu_exact(float v)
{
    return 0.5f * v * (1.0f + erff(v * 0.70710678118654752f));
}

template <int EPI>
__global__ void gemm_kernel(const float* __restrict__ A,
                            const float* __restrict__ Bw,
                            const float* __restrict__ bias,
                            const float* __restrict__ res,
                            const float* __restrict__ gate, int gate_off,
                            float* __restrict__ C,
                            int M, int N, int K)
{
    __shared__ float As[BK][BM];
    __shared__ float Bs[BK][BN];

    int tid = threadIdx.x;
    int bx = blockIdx.x, by = blockIdx.y;
    int tr = tid >> 4, tc = tid & 15;       // 16 x 16 thread grid

    float acc[8][8];
#pragma unroll
    for (int i = 0; i < 8; i++)
#pragma unroll
        for (int j = 0; j < 8; j++) acc[i][j] = 0.f;

    int lrow = tid >> 1;
    int lc4  = (tid & 1) * 4;
    const float* Aptr = A  + (size_t)(by * BM + lrow) * K + lc4;
    const float* Bptr = Bw + (size_t)(bx * BN + lrow) * K + lc4;

    for (int k0 = 0; k0 < K; k0 += BK) {
        float4 a4 = *(const float4*)(Aptr + k0);
        float4 b4 = *(const float4*)(Bptr + k0);
        As[lc4 + 0][lrow] = a4.x; As[lc4 + 1][lrow] = a4.y;
        As[lc4 + 2][lrow] = a4.z; As[lc4 + 3][lrow] = a4.w;
        Bs[lc4 + 0][lrow] = b4.x; Bs[lc4 + 1][lrow] = b4.y;
        Bs[lc4 + 2][lrow] = b4.z; Bs[lc4 + 3][lrow] = b4.w;
        __syncthreads();

#pragma unroll
        for (int kk = 0; kk < BK; kk++) {
            float a[8], b[8];
            const float4* ap = (const float4*)(&As[kk][tr * 8]);
            const float4* bp = (const float4*)(&Bs[kk][tc * 8]);
            float4 a0 = ap[0], a1 = ap[1];
            float4 b0 = bp[0], b1 = bp[1];
            a[0]=a0.x; a[1]=a0.y; a[2]=a0.z; a[3]=a0.w;
            a[4]=a1.x; a[5]=a1.y; a[6]=a1.z; a[7]=a1.w;
            b[0]=b0.x; b[1]=b0.y; b[2]=b0.z; b[3]=b0.w;
            b[4]=b1.x; b[5]=b1.y; b[6]=b1.z; b[7]=b1.w;
#pragma unroll
            for (int i = 0; i < 8; i++)
#pragma unroll
                for (int j = 0; j < 8; j++)
                    acc[i][j] += a[i] * b[j];
        }
        __syncthreads();
    }

    // Epilogue
#pragma unroll
    for (int i = 0; i < 8; i++) {
        int m = by * BM + tr * 8 + i;
        size_t mrow = (size_t)m * N;
        size_t grow = (size_t)m * MODC + gate_off;
#pragma unroll
        for (int j = 0; j < 8; j++) {
            int n = bx * BN + tc * 8 + j;
            float v = acc[i][j];
            if (bias) v += bias[n];
            if (EPI == 1) v = gelu_exact(v);
            if (EPI == 2) v = res[mrow + n] + gate[grow + n] * v;
            C[mrow + n] = v;
        }
    }
}

// ---------------------------------------------------------------------------
// Causal attention, fp32 "flash-lite".
// Scores are tiny (std ~0.2) so softmax needs no max-subtraction:
// p = exp(s/8), l = sum p, o = sum p*v, out = o/l  (identical math to ref).
// Block: 256 threads = 128 queries x 2 half-threads (32 dims each).
// Grid: (T/128, H, B). K/V staged in 64-key smem tiles.
// ---------------------------------------------------------------------------
__global__ void attn_kernel(const float* __restrict__ qkv, float* __restrict__ out)
{
    int b  = blockIdx.z;
    int h  = blockIdx.y;
    int qt = blockIdx.x;
    int t  = threadIdx.x;
    int qi   = qt * 128 + (t >> 1);     // query index
    int half = t & 1;                   // which 32-dim half

    __shared__ float Ks[64][64];
    __shared__ float Vs[64][64];

    // Load q (32 floats for this half)
    const float* qrow = qkv + ((size_t)(b * Tt + qi)) * (3 * DIMd) + h * DHEAD + half * 32;
    float q[32];
#pragma unroll
    for (int j = 0; j < 8; j++) {
        float4 qq = *(const float4*)(qrow + j * 4);
        q[4*j+0] = qq.x; q[4*j+1] = qq.y; q[4*j+2] = qq.z; q[4*j+3] = qq.w;
    }

    float o[32];
#pragma unroll
    for (int j = 0; j < 32; j++) o[j] = 0.f;
    float l = 0.f;

    int ntiles = qt * 2 + 2;            // keys up to qt*128+127
    for (int tile = 0; tile < ntiles; tile++) {
        int k0 = tile * 64;
        // Stage K/V tile: 64 rows x 64 dims each
        for (int i = t; i < 64 * 16; i += 256) {
            int row = i >> 4;
            int c4  = i & 15;
            size_t base = ((size_t)(b * Tt + k0 + row)) * (3 * DIMd) + h * DHEAD + c4 * 4;
            *(float4*)&Ks[row][c4 * 4] = *(const float4*)(qkv + base + DIMd);
            *(float4*)&Vs[row][c4 * 4] = *(const float4*)(qkv + base + 2 * DIMd);
        }
        __syncthreads();

        for (int kk = 0; kk < 64; kk++) {
            const float4* kp = (const float4*)(&Ks[kk][half * 32]);
            float s0 = 0.f, s1 = 0.f, s2 = 0.f, s3 = 0.f;
#pragma unroll
            for (int j = 0; j < 8; j++) {
                float4 kv = kp[j];
                s0 += q[4*j+0] * kv.x;
                s1 += q[4*j+1] * kv.y;
                s2 += q[4*j+2] * kv.z;
                s3 += q[4*j+3] * kv.w;
            }
            float s = (s0 + s1) + (s2 + s3);
            s += __shfl_xor_sync(0xffffffffu, s, 1);   // full 64-dim dot
            float p = (k0 + kk <= qi) ? __expf(s * 0.125f) : 0.0f;
            l += p;
            const float4* vp = (const float4*)(&Vs[kk][half * 32]);
#pragma unroll
            for (int j = 0; j < 8; j++) {
                float4 vv = vp[j];
                o[4*j+0] += p * vv.x;
                o[4*j+1] += p * vv.y;
                o[4*j+2] += p * vv.z;
                o[4*j+3] += p * vv.w;
            }
        }
        __syncthreads();
    }

    float inv = 1.0f / l;
    float* orow = out + ((size_t)(b * Tt + qi)) * DIMd + h * DHEAD + half * 32;
#pragma unroll
    for (int j = 0; j < 8; j++) {
        float4 ov;
        ov.x = o[4*j+0] * inv; ov.y = o[4*j+1] * inv;
        ov.z = o[4*j+2] * inv; ov.w = o[4*j+3] * inv;
        *(float4*)(orow + j * 4) = ov;
    }
}

// ---------------------------------------------------------------------------
// Launch
// Inputs (metadata order): 0:x 1:action_emb 2:causal_mask 3:Wqkv 4:Wout 5:bout
//                          6:W1 7:b1 8:W2 9:b2 10:Wmod 11:bmod
// ---------------------------------------------------------------------------
extern "C" void kernel_launch(void* const* d_in, const int* in_sizes, int n_in,
                              void* d_out, int out_size)
{
    const float* x    = (const float*)d_in[0];
    const float* aemb = (const float*)d_in[1];
    const float* Wqkv = (const float*)d_in[3];
    const float* Wout = (const float*)d_in[4];
    const float* bout = (const float*)d_in[5];
    const float* W1   = (const float*)d_in[6];
    const float* b1   = (const float*)d_in[7];
    const float* W2   = (const float*)d_in[8];
    const float* b2   = (const float*)d_in[9];
    const float* Wmod = (const float*)d_in[10];
    const float* bmod = (const float*)d_in[11];
    float* out = (float*)d_out;

    float *silu_p, *mod_p, *h_p, *qkv_p, *attn_p, *x1_p, *mlp_p;
    cudaGetSymbolAddress((void**)&silu_p, g_silu);
    cudaGetSymbolAddress((void**)&mod_p,  g_mod);
    cudaGetSymbolAddress((void**)&h_p,    g_h);
    cudaGetSymbolAddress((void**)&qkv_p,  g_qkv);
    cudaGetSymbolAddress((void**)&attn_p, g_attn);
    cudaGetSymbolAddress((void**)&x1_p,   g_x1);
    cudaGetSymbolAddress((void**)&mlp_p,  g_mlp);

    // 1) silu(action_emb)
    silu_kernel<<<(NTOK * ADIM + 255) / 256, 256>>>(aemb, silu_p, NTOK * ADIM);

    // 2) mod = silu_a @ Wmod^T + bmod   [8192 x 3072], K=256
    gemm_kernel<0><<<dim3(MODC / BN, NTOK / BM), 256>>>(
        silu_p, Wmod, bmod, nullptr, nullptr, 0, mod_p, NTOK, MODC, ADIM);

    // 3) h = LN(x)*(1+scale1)+shift1
    lnmod_kernel<<<NTOK, 128>>>(x, mod_p, 0, DIMd, h_p);

    // 4) qkv = h @ Wqkv^T  [8192 x 1536], K=512
    gemm_kernel<0><<<dim3((3 * DIMd) / BN, NTOK / BM), 256>>>(
        h_p, Wqkv, nullptr, nullptr, nullptr, 0, qkv_p, NTOK, 3 * DIMd, DIMd);

    // 5) causal attention -> g_attn [8192 x 512]
    attn_kernel<<<dim3(Tt / 128, NHEAD, Bb), 256>>>(qkv_p, attn_p);

    // 6) x1 = x + gate1 * (attn @ Wout^T + bout)
    gemm_kernel<2><<<dim3(DIMd / BN, NTOK / BM), 256>>>(
        attn_p, Wout, bout, x, mod_p, 2 * DIMd, x1_p, NTOK, DIMd, DIMd);

    // 7) h = LN(x1)*(1+scale2)+shift2
    lnmod_kernel<<<NTOK, 128>>>(x1_p, mod_p, 3 * DIMd, 4 * DIMd, h_p);

    // 8) mlp = gelu(h @ W1^T + b1)  [8192 x 2048], K=512
    gemm_kernel<1><<<dim3(MLPD / BN, NTOK / BM), 256>>>(
        h_p, W1, b1, nullptr, nullptr, 0, mlp_p, NTOK, MLPD, DIMd);

    // 9) out = x1 + gate2 * (mlp @ W2^T + b2)  K=2048
    gemm_kernel<2><<<dim3(DIMd / BN, NTOK / BM), 256>>>(
        mlp_p, W2, b2, x1_p, mod_p, 5 * DIMd, out, NTOK, DIMd, MLPD);
}

// round 3
// speedup vs baseline: 1.8123x; 1.8123x over previous
#include <cuda_runtime.h>
#include <cuda_bf16.h>
#include <math.h>
#include <stdint.h>
#include <cstdint>

// Problem constants
#define Bb     4
#define Tt     2048
#define DIMd   512
#define NHEAD  8
#define DHEAD  64
#define MLPD   2048
#define ADIM   256
#define NTOK   (Bb * Tt)          // 8192 tokens
#define MODC   (6 * DIMd)         // 3072 modulation cols

typedef __nv_bfloat16 bf16;

// ---------------------------------------------------------------------------
// Scratch (static device globals; allocation-free per harness rules)
// ---------------------------------------------------------------------------
__device__ float g_mod [(size_t)NTOK * MODC];    // 100.7 MB fp32 (shift/scale/gate)
__device__ float g_qkv [NTOK * 3 * DIMd];        // 50.3 MB fp32 (attention input)
__device__ float g_x1  [NTOK * DIMd];            // 16.8 MB fp32 (residual stream)

__device__ bf16 g_silu_bf[NTOK * ADIM];
__device__ bf16 g_h_bf   [NTOK * DIMd];
__device__ bf16 g_attn_bf[NTOK * DIMd];
__device__ bf16 g_mlp_bf [(size_t)NTOK * MLPD];

__device__ bf16 g_Wqkv_bf[3 * DIMd * DIMd];
__device__ bf16 g_Wout_bf[DIMd * DIMd];
__device__ bf16 g_W1_bf  [MLPD * DIMd];
__device__ bf16 g_W2_bf  [DIMd * MLPD];
__device__ bf16 g_Wmod_bf[MODC * ADIM];

// ---------------------------------------------------------------------------
// fp32 -> bf16 weight conversion
// ---------------------------------------------------------------------------
__global__ void f2bf_kernel(const float* __restrict__ in, bf16* __restrict__ out, int n)
{
    int i = blockIdx.x * blockDim.x + threadIdx.x;
    if (i < n) out[i] = __float2bfloat16(in[i]);
}

// ---------------------------------------------------------------------------
// SiLU elementwise -> bf16
// ---------------------------------------------------------------------------
__global__ void silu_kernel(const float* __restrict__ a, bf16* __restrict__ out, int n)
{
    int i = blockIdx.x * blockDim.x + threadIdx.x;
    if (i < n) {
        float v = a[i];
        out[i] = __float2bfloat16(v / (1.0f + __expf(-v)));
    }
}

// ---------------------------------------------------------------------------
// Fused LayerNorm + AdaLN modulation -> bf16: out = LN(x)*(1+scale)+shift
// ---------------------------------------------------------------------------
__global__ void lnmod_kernel(const float* __restrict__ x,
                             const float* __restrict__ mod,
                             int shift_off, int scale_off,
                             bf16* __restrict__ out)
{
    int row = blockIdx.x;
    int t   = threadIdx.x;
    const float* xr = x + (size_t)row * DIMd;

    float v[4];
    float s1 = 0.f, s2 = 0.f;
#pragma unroll
    for (int j = 0; j < 4; j++) {
        float z = xr[t + j * 128];
        v[j] = z; s1 += z; s2 += z * z;
    }
#pragma unroll
    for (int off = 16; off; off >>= 1) {
        s1 += __shfl_xor_sync(0xffffffffu, s1, off);
        s2 += __shfl_xor_sync(0xffffffffu, s2, off);
    }
    __shared__ float r1[4], r2[4];
    int w = t >> 5;
    if ((t & 31) == 0) { r1[w] = s1; r2[w] = s2; }
    __syncthreads();
    s1 = r1[0] + r1[1] + r1[2] + r1[3];
    s2 = r2[0] + r2[1] + r2[2] + r2[3];

    float mu   = s1 * (1.0f / DIMd);
    float var  = s2 * (1.0f / DIMd) - mu * mu;
    float rstd = rsqrtf(var + 1e-5f);

    const float* mrow = mod + (size_t)row * MODC;
    bf16* orow = out + (size_t)row * DIMd;
#pragma unroll
    for (int j = 0; j < 4; j++) {
        int c = t + j * 128;
        float sc = mrow[scale_off + c];
        float sh = mrow[shift_off + c];
        orow[c] = __float2bfloat16((v[j] - mu) * rstd * (1.0f + sc) + sh);
    }
}

// ---------------------------------------------------------------------------
// bf16 tensor-core GEMM: C[M,N] = A[M,K] @ B[N,K]^T (+bias) (+epilogue)
// 128x128x32 tiles, 256 threads (8 warps, 2x4 warp grid, 64x32 warp tiles),
// mma.sync.m16n8k16 bf16, cp.async double-buffered smem, ldmatrix x4.
// EPI: 0 = +bias, fp32 out
//      1 = exact GELU(acc+bias), bf16 out
//      2 = res + gate*(acc+bias), fp32 out
// ---------------------------------------------------------------------------
#define GBM 128
#define GBN 128
#define GBK 32
#define GSTR (GBK + 8)     // padded smem row stride (elems): 40 -> 80B, 16B-mult

__device__ __forceinline__ float gelu_exact(float v)
{
    return 0.5f * v * (1.0f + erff(v * 0.70710678118654752f));
}

template <int EPI>
__global__ void __launch_bounds__(256) mma_gemm(
    const bf16* __restrict__ A,
    const bf16* __restrict__ Bw,
    const float* __restrict__ bias,
    const float* __restrict__ res,
    const float* __restrict__ gate, int gate_off,
    void* __restrict__ Cout,
    int M, int N, int K)
{
    __shared__ bf16 As[2][GBM * GSTR];
    __shared__ bf16 Bs[2][GBN * GSTR];

    const int tid  = threadIdx.x;
    const int bx   = blockIdx.x, by = blockIdx.y;
    const int wid  = tid >> 5, lane = tid & 31;
    const int wm   = wid & 1;         // 0..1  (64-row slab)
    const int wn   = wid >> 1;        // 0..3  (32-col slab)

    // global->smem load mapping: 16B per task, 2 passes of 64 rows
    const int lr = tid >> 2;          // row 0..63
    const int lc = (tid & 3) * 8;     // col chunk (elems)
    const bf16* Ag = A  + (size_t)(by * GBM) * K;
    const bf16* Bg = Bw + (size_t)(bx * GBN) * K;

    float acc[4][4][4];
#pragma unroll
    for (int i = 0; i < 4; i++)
#pragma unroll
        for (int j = 0; j < 4; j++)
#pragma unroll
            for (int r = 0; r < 4; r++) acc[i][j][r] = 0.f;

    const int KT = K / GBK;

#define ISSUE_TILE(kt, buf)                                                        \
    {                                                                              \
        int k0_ = (kt) * GBK;                                                      \
        _Pragma("unroll")                                                          \
        for (int p = 0; p < 2; p++) {                                              \
            int row_ = lr + p * 64;                                                \
            unsigned sA_ = (unsigned)__cvta_generic_to_shared(                     \
                &As[buf][row_ * GSTR + lc]);                                       \
            asm volatile("cp.async.cg.shared.global [%0], [%1], 16;\n"             \
                         :: "r"(sA_), "l"(Ag + (size_t)row_ * K + k0_ + lc));      \
            unsigned sB_ = (unsigned)__cvta_generic_to_shared(                     \
                &Bs[buf][row_ * GSTR + lc]);                                       \
            asm volatile("cp.async.cg.shared.global [%0], [%1], 16;\n"             \
                         :: "r"(sB_), "l"(Bg + (size_t)row_ * K + k0_ + lc));      \
        }                                                                          \
        asm volatile("cp.async.commit_group;\n" ::: "memory");                     \
    }

    ISSUE_TILE(0, 0);

    for (int kt = 0; kt < KT; kt++) {
        const int buf = kt & 1;
        if (kt + 1 < KT) {
            ISSUE_TILE(kt + 1, buf ^ 1);
            asm volatile("cp.async.wait_group 1;\n" ::: "memory");
        } else {
            asm volatile("cp.async.wait_group 0;\n" ::: "memory");
        }
        __syncthreads();

#pragma unroll
        for (int ks = 0; ks < 2; ks++) {
            const int kk = ks * 16;

            // A fragments: 4 m16k16 tiles
            unsigned aF[4][4];
#pragma unroll
            for (int i = 0; i < 4; i++) {
                int row = wm * 64 + i * 16 + (lane & 7) + ((lane >> 3) & 1) * 8;
                int col = kk + (lane >> 4) * 8;
                unsigned addr = (unsigned)__cvta_generic_to_shared(
                    &As[buf][row * GSTR + col]);
                asm volatile(
                    "ldmatrix.sync.aligned.m8n8.x4.shared.b16 {%0,%1,%2,%3}, [%4];\n"
                    : "=r"(aF[i][0]), "=r"(aF[i][1]), "=r"(aF[i][2]), "=r"(aF[i][3])
                    : "r"(addr));
            }

            // B fragments: 4 n8k16 tiles via 2 x4 loads
            unsigned bF[4][2];
#pragma unroll
            for (int j = 0; j < 2; j++) {
                int row = wn * 32 + j * 16 + (lane >> 4) * 8 + (lane & 7);
                int col = kk + ((lane >> 3) & 1) * 8;
                unsigned addr = (unsigned)__cvta_generic_to_shared(
                    &Bs[buf][row * GSTR + col]);
                unsigned r0, r1, r2, r3;
                asm volatile(
                    "ldmatrix.sync.aligned.m8n8.x4.shared.b16 {%0,%1,%2,%3}, [%4];\n"
                    : "=r"(r0), "=r"(r1), "=r"(r2), "=r"(r3)
                    : "r"(addr));
                bF[2 * j + 0][0] = r0; bF[2 * j + 0][1] = r1;
                bF[2 * j + 1][0] = r2; bF[2 * j + 1][1] = r3;
            }

#pragma unroll
            for (int i = 0; i < 4; i++)
#pragma unroll
                for (int j = 0; j < 4; j++) {
                    asm volatile(
                        "mma.sync.aligned.m16n8k16.row.col.f32.bf16.bf16.f32 "
                        "{%0,%1,%2,%3}, {%4,%5,%6,%7}, {%8,%9}, {%0,%1,%2,%3};\n"
                        : "+f"(acc[i][j][0]), "+f"(acc[i][j][1]),
                          "+f"(acc[i][j][2]), "+f"(acc[i][j][3])
                        : "r"(aF[i][0]), "r"(aF[i][1]), "r"(aF[i][2]), "r"(aF[i][3]),
                          "r"(bF[j][0]), "r"(bF[j][1]));
                }
        }
        __syncthreads();
    }
#undef ISSUE_TILE

    // Epilogue. acc layout: c0,c1 = (row=lane/4, col=2*(lane%4)+{0,1}); c2,c3 = row+8
    const int grp = lane >> 2;
    const int qd  = (lane & 3) * 2;
#pragma unroll
    for (int i = 0; i < 4; i++) {
#pragma unroll
        for (int half = 0; half < 2; half++) {
            int m = by * GBM + wm * 64 + i * 16 + grp + half * 8;
            size_t crow = (size_t)m * N;
            size_t grow = (size_t)m * MODC + gate_off;
#pragma unroll
            for (int j = 0; j < 4; j++) {
                int n = bx * GBN + wn * 32 + j * 8 + qd;
                float v0 = acc[i][j][half * 2 + 0];
                float v1 = acc[i][j][half * 2 + 1];
                if (bias) { v0 += bias[n]; v1 += bias[n + 1]; }
                if (EPI == 1) {
                    v0 = gelu_exact(v0); v1 = gelu_exact(v1);
                    bf16* C = (bf16*)Cout;
                    C[crow + n]     = __float2bfloat16(v0);
                    C[crow + n + 1] = __float2bfloat16(v1);
                } else if (EPI == 2) {
                    float* C = (float*)Cout;
                    C[crow + n]     = res[crow + n]     + gate[grow + n]     * v0;
                    C[crow + n + 1] = res[crow + n + 1] + gate[grow + n + 1] * v1;
                } else {
                    float* C = (float*)Cout;
                    C[crow + n]     = v0;
                    C[crow + n + 1] = v1;
                }
            }
        }
    }
}

// ---------------------------------------------------------------------------
// Causal attention, fp32 "flash-lite" (scores tiny -> no max subtraction).
// 256 threads = 128 queries x 2 half-threads; 64-key K/V smem tiles.
// Output written as bf16 (feeds Wout GEMM).
// ---------------------------------------------------------------------------
__global__ void attn_kernel(const float* __restrict__ qkv, bf16* __restrict__ out)
{
    int b  = blockIdx.z;
    int h  = blockIdx.y;
    int qt = blockIdx.x;
    int t  = threadIdx.x;
    int qi   = qt * 128 + (t >> 1);
    int half = t & 1;

    __shared__ float Ks[64][64];
    __shared__ float Vs[64][64];

    const float* qrow = qkv + ((size_t)(b * Tt + qi)) * (3 * DIMd) + h * DHEAD + half * 32;
    float q[32];
#pragma unroll
    for (int j = 0; j < 8; j++) {
        float4 qq = *(const float4*)(qrow + j * 4);
        q[4*j+0] = qq.x; q[4*j+1] = qq.y; q[4*j+2] = qq.z; q[4*j+3] = qq.w;
    }

    float o[32];
#pragma unroll
    for (int j = 0; j < 32; j++) o[j] = 0.f;
    float l = 0.f;

    int ntiles = qt * 2 + 2;
    for (int tile = 0; tile < ntiles; tile++) {
        int k0 = tile * 64;
        for (int i = t; i < 64 * 16; i += 256) {
            int row = i >> 4;
            int c4  = i & 15;
            size_t base = ((size_t)(b * Tt + k0 + row)) * (3 * DIMd) + h * DHEAD + c4 * 4;
            *(float4*)&Ks[row][c4 * 4] = *(const float4*)(qkv + base + DIMd);
            *(float4*)&Vs[row][c4 * 4] = *(const float4*)(qkv + base + 2 * DIMd);
        }
        __syncthreads();

        for (int kk = 0; kk < 64; kk++) {
            const float4* kp = (const float4*)(&Ks[kk][half * 32]);
            float s0 = 0.f, s1 = 0.f, s2 = 0.f, s3 = 0.f;
#pragma unroll
            for (int j = 0; j < 8; j++) {
                float4 kv = kp[j];
                s0 += q[4*j+0] * kv.x;
                s1 += q[4*j+1] * kv.y;
                s2 += q[4*j+2] * kv.z;
                s3 += q[4*j+3] * kv.w;
            }
            float s = (s0 + s1) + (s2 + s3);
            s += __shfl_xor_sync(0xffffffffu, s, 1);
            float p = (k0 + kk <= qi) ? __expf(s * 0.125f) : 0.0f;
            l += p;
            const float4* vp = (const float4*)(&Vs[kk][half * 32]);
#pragma unroll
            for (int j = 0; j < 8; j++) {
                float4 vv = vp[j];
                o[4*j+0] += p * vv.x;
                o[4*j+1] += p * vv.y;
                o[4*j+2] += p * vv.z;
                o[4*j+3] += p * vv.w;
            }
        }
        __syncthreads();
    }

    float inv = 1.0f / l;
    __nv_bfloat162* orow =
        (__nv_bfloat162*)(out + ((size_t)(b * Tt + qi)) * DIMd + h * DHEAD + half * 32);
#pragma unroll
    for (int j = 0; j < 16; j++) {
        orow[j] = __floats2bfloat162_rn(o[2*j] * inv, o[2*j+1] * inv);
    }
}

// ---------------------------------------------------------------------------
// Launch
// Inputs: 0:x 1:action_emb 2:causal_mask 3:Wqkv 4:Wout 5:bout
//         6:W1 7:b1 8:W2 9:b2 10:Wmod 11:bmod
// ---------------------------------------------------------------------------
extern "C" void kernel_launch(void* const* d_in, const int* in_sizes, int n_in,
                              void* d_out, int out_size)
{
    const float* x    = (const float*)d_in[0];
    const float* aemb = (const float*)d_in[1];
    const float* Wqkv = (const float*)d_in[3];
    const float* Wout = (const float*)d_in[4];
    const float* bout = (const float*)d_in[5];
    const float* W1   = (const float*)d_in[6];
    const float* b1   = (const float*)d_in[7];
    const float* W2   = (const float*)d_in[8];
    const float* b2   = (const float*)d_in[9];
    const float* Wmod = (const float*)d_in[10];
    const float* bmod = (const float*)d_in[11];
    float* out = (float*)d_out;

    float *mod_p, *qkv_p, *x1_p;
    bf16 *silu_p, *h_p, *attn_p, *mlp_p;
    bf16 *wqkv_p, *wout_p, *w1_p, *w2_p, *wmod_p;
    cudaGetSymbolAddress((void**)&mod_p,  g_mod);
    cudaGetSymbolAddress((void**)&qkv_p,  g_qkv);
    cudaGetSymbolAddress((void**)&x1_p,   g_x1);
    cudaGetSymbolAddress((void**)&silu_p, g_silu_bf);
    cudaGetSymbolAddress((void**)&h_p,    g_h_bf);
    cudaGetSymbolAddress((void**)&attn_p, g_attn_bf);
    cudaGetSymbolAddress((void**)&mlp_p,  g_mlp_bf);
    cudaGetSymbolAddress((void**)&wqkv_p, g_Wqkv_bf);
    cudaGetSymbolAddress((void**)&wout_p, g_Wout_bf);
    cudaGetSymbolAddress((void**)&w1_p,   g_W1_bf);
    cudaGetSymbolAddress((void**)&w2_p,   g_W2_bf);
    cudaGetSymbolAddress((void**)&wmod_p, g_Wmod_bf);

    // Weight conversions (cheap, ~4M elems total)
    f2bf_kernel<<<(3*DIMd*DIMd + 255)/256, 256>>>(Wqkv, wqkv_p, 3*DIMd*DIMd);
    f2bf_kernel<<<(DIMd*DIMd + 255)/256, 256>>>(Wout, wout_p, DIMd*DIMd);
    f2bf_kernel<<<(MLPD*DIMd + 255)/256, 256>>>(W1, w1_p, MLPD*DIMd);
    f2bf_kernel<<<(DIMd*MLPD + 255)/256, 256>>>(W2, w2_p, DIMd*MLPD);
    f2bf_kernel<<<(MODC*ADIM + 255)/256, 256>>>(Wmod, wmod_p, MODC*ADIM);

    // 1) silu(action_emb) -> bf16
    silu_kernel<<<(NTOK * ADIM + 255) / 256, 256>>>(aemb, silu_p, NTOK * ADIM);

    // 2) mod = silu_a @ Wmod^T + bmod  [8192 x 3072] K=256, fp32 out
    mma_gemm<0><<<dim3(MODC / GBN, NTOK / GBM), 256>>>(
        silu_p, wmod_p, bmod, nullptr, nullptr, 0, mod_p, NTOK, MODC, ADIM);

    // 3) h = LN(x)*(1+scale1)+shift1 -> bf16
    lnmod_kernel<<<NTOK, 128>>>(x, mod_p, 0, DIMd, h_p);

    // 4) qkv = h @ Wqkv^T  [8192 x 1536] K=512, fp32 out
    mma_gemm<0><<<dim3((3 * DIMd) / GBN, NTOK / GBM), 256>>>(
        h_p, wqkv_p, nullptr, nullptr, nullptr, 0, qkv_p, NTOK, 3 * DIMd, DIMd);

    // 5) causal attention -> bf16
    attn_kernel<<<dim3(Tt / 128, NHEAD, Bb), 256>>>(qkv_p, attn_p);

    // 6) x1 = x + gate1 * (attn @ Wout^T + bout)  fp32 out
    mma_gemm<2><<<dim3(DIMd / GBN, NTOK / GBM), 256>>>(
        attn_p, wout_p, bout, x, mod_p, 2 * DIMd, x1_p, NTOK, DIMd, DIMd);

    // 7) h = LN(x1)*(1+scale2)+shift2 -> bf16
    lnmod_kernel<<<NTOK, 128>>>(x1_p, mod_p, 3 * DIMd, 4 * DIMd, h_p);

    // 8) mlp = gelu(h @ W1^T + b1)  [8192 x 2048] K=512, bf16 out
    mma_gemm<1><<<dim3(MLPD / GBN, NTOK / GBM), 256>>>(
        h_p, w1_p, b1, nullptr, nullptr, 0, mlp_p, NTOK, MLPD, DIMd);

    // 9) out = x1 + gate2 * (mlp @ W2^T + b2)  K=2048, fp32 out
    mma_gemm<2><<<dim3(DIMd / GBN, NTOK / GBM), 256>>>(
        mlp_p, w2_p, b2, x1_p, mod_p, 5 * DIMd, out, NTOK, DIMd, MLPD);
}

// round 4
// speedup vs baseline: 4.7453x; 2.6183x over previous
#include <cuda_runtime.h>
#include <cuda_bf16.h>
#include <math.h>

// Problem constants
#define Bb     4
#define Tt     2048
#define DIMd   512
#define NHEAD  8
#define DHEAD  64
#define MLPD   2048
#define ADIM   256
#define NTOK   (Bb * Tt)          // 8192 tokens
#define MODC   (6 * DIMd)         // 3072 modulation cols
#define QKVC   (3 * DIMd)         // 1536

typedef __nv_bfloat16 bf16;

// ---------------------------------------------------------------------------
// Scratch (static device globals; allocation-free per harness rules)
// ---------------------------------------------------------------------------
__device__ float g_mod [(size_t)NTOK * MODC];    // fp32 shift/scale/gate
__device__ float g_x1  [NTOK * DIMd];            // fp32 residual stream

__device__ bf16 g_silu_bf[NTOK * ADIM];
__device__ bf16 g_h_bf   [NTOK * DIMd];
__device__ bf16 g_qkv_bf [(size_t)NTOK * QKVC];
__device__ bf16 g_attn_bf[NTOK * DIMd];
__device__ bf16 g_mlp_bf [(size_t)NTOK * MLPD];

__device__ bf16 g_Wqkv_bf[QKVC * DIMd];
__device__ bf16 g_Wout_bf[DIMd * DIMd];
__device__ bf16 g_W1_bf  [MLPD * DIMd];
__device__ bf16 g_W2_bf  [DIMd * MLPD];
__device__ bf16 g_Wmod_bf[MODC * ADIM];

// ---------------------------------------------------------------------------
// fp32 -> bf16 conversion / SiLU
// ---------------------------------------------------------------------------
__global__ void f2bf_kernel(const float* __restrict__ in, bf16* __restrict__ out, int n)
{
    int i = blockIdx.x * blockDim.x + threadIdx.x;
    if (i < n) out[i] = __float2bfloat16(in[i]);
}

__global__ void silu_kernel(const float* __restrict__ a, bf16* __restrict__ out, int n)
{
    int i = blockIdx.x * blockDim.x + threadIdx.x;
    if (i < n) {
        float v = a[i];
        out[i] = __float2bfloat16(v / (1.0f + __expf(-v)));
    }
}

// ---------------------------------------------------------------------------
// Fused LayerNorm + AdaLN modulation -> bf16
// ---------------------------------------------------------------------------
__global__ void lnmod_kernel(const float* __restrict__ x,
                             const float* __restrict__ mod,
                             int shift_off, int scale_off,
                             bf16* __restrict__ out)
{
    int row = blockIdx.x;
    int t   = threadIdx.x;
    const float* xr = x + (size_t)row * DIMd;

    float v[4];
    float s1 = 0.f, s2 = 0.f;
#pragma unroll
    for (int j = 0; j < 4; j++) {
        float z = xr[t + j * 128];
        v[j] = z; s1 += z; s2 += z * z;
    }
#pragma unroll
    for (int off = 16; off; off >>= 1) {
        s1 += __shfl_xor_sync(0xffffffffu, s1, off);
        s2 += __shfl_xor_sync(0xffffffffu, s2, off);
    }
    __shared__ float r1[4], r2[4];
    int w = t >> 5;
    if ((t & 31) == 0) { r1[w] = s1; r2[w] = s2; }
    __syncthreads();
    s1 = r1[0] + r1[1] + r1[2] + r1[3];
    s2 = r2[0] + r2[1] + r2[2] + r2[3];

    float mu   = s1 * (1.0f / DIMd);
    float var  = s2 * (1.0f / DIMd) - mu * mu;
    float rstd = rsqrtf(var + 1e-5f);

    const float* mrow = mod + (size_t)row * MODC;
    bf16* orow = out + (size_t)row * DIMd;
#pragma unroll
    for (int j = 0; j < 4; j++) {
        int c = t + j * 128;
        float sc = mrow[scale_off + c];
        float sh = mrow[shift_off + c];
        orow[c] = __float2bfloat16((v[j] - mu) * rstd * (1.0f + sc) + sh);
    }
}

// ---------------------------------------------------------------------------
// bf16 tensor-core GEMM: C[M,N] = A[M,K] @ B[N,K]^T (+bias) (+epilogue)
// EPI: 0 = +bias fp32 out, 1 = GELU(acc+bias) bf16 out,
//      2 = res + gate*(acc+bias) fp32 out, 3 = acc(+bias) bf16 out
// ---------------------------------------------------------------------------
#define GBM 128
#define GBN 128
#define GBK 32
#define GSTR (GBK + 8)

__device__ __forceinline__ float gelu_exact(float v)
{
    return 0.5f * v * (1.0f + erff(v * 0.70710678118654752f));
}

template <int EPI>
__global__ void __launch_bounds__(256) mma_gemm(
    const bf16* __restrict__ A,
    const bf16* __restrict__ Bw,
    const float* __restrict__ bias,
    const float* __restrict__ res,
    const float* __restrict__ gate, int gate_off,
    void* __restrict__ Cout,
    int M, int N, int K)
{
    __shared__ bf16 As[2][GBM * GSTR];
    __shared__ bf16 Bs[2][GBN * GSTR];

    const int tid  = threadIdx.x;
    const int bx   = blockIdx.x, by = blockIdx.y;
    const int wid  = tid >> 5, lane = tid & 31;
    const int wm   = wid & 1;
    const int wn   = wid >> 1;

    const int lr = tid >> 2;
    const int lc = (tid & 3) * 8;
    const bf16* Ag = A  + (size_t)(by * GBM) * K;
    const bf16* Bg = Bw + (size_t)(bx * GBN) * K;

    float acc[4][4][4];
#pragma unroll
    for (int i = 0; i < 4; i++)
#pragma unroll
        for (int j = 0; j < 4; j++)
#pragma unroll
            for (int r = 0; r < 4; r++) acc[i][j][r] = 0.f;

    const int KT = K / GBK;

#define ISSUE_TILE(kt, buf)                                                        \
    {                                                                              \
        int k0_ = (kt) * GBK;                                                      \
        _Pragma("unroll")                                                          \
        for (int p = 0; p < 2; p++) {                                              \
            int row_ = lr + p * 64;                                                \
            unsigned sA_ = (unsigned)__cvta_generic_to_shared(                     \
                &As[buf][row_ * GSTR + lc]);                                       \
            asm volatile("cp.async.cg.shared.global [%0], [%1], 16;\n"             \
                         :: "r"(sA_), "l"(Ag + (size_t)row_ * K + k0_ + lc));      \
            unsigned sB_ = (unsigned)__cvta_generic_to_shared(                     \
                &Bs[buf][row_ * GSTR + lc]);                                       \
            asm volatile("cp.async.cg.shared.global [%0], [%1], 16;\n"             \
                         :: "r"(sB_), "l"(Bg + (size_t)row_ * K + k0_ + lc));      \
        }                                                                          \
        asm volatile("cp.async.commit_group;\n" ::: "memory");                     \
    }

    ISSUE_TILE(0, 0);

    for (int kt = 0; kt < KT; kt++) {
        const int buf = kt & 1;
        if (kt + 1 < KT) {
            ISSUE_TILE(kt + 1, buf ^ 1);
            asm volatile("cp.async.wait_group 1;\n" ::: "memory");
        } else {
            asm volatile("cp.async.wait_group 0;\n" ::: "memory");
        }
        __syncthreads();

#pragma unroll
        for (int ks = 0; ks < 2; ks++) {
            const int kk = ks * 16;

            unsigned aF[4][4];
#pragma unroll
            for (int i = 0; i < 4; i++) {
                int row = wm * 64 + i * 16 + (lane & 15);
                int col = kk + (lane >> 4) * 8;
                unsigned addr = (unsigned)__cvta_generic_to_shared(
                    &As[buf][row * GSTR + col]);
                asm volatile(
                    "ldmatrix.sync.aligned.m8n8.x4.shared.b16 {%0,%1,%2,%3}, [%4];\n"
                    : "=r"(aF[i][0]), "=r"(aF[i][1]), "=r"(aF[i][2]), "=r"(aF[i][3])
                    : "r"(addr));
            }

            unsigned bF[4][2];
#pragma unroll
            for (int j = 0; j < 2; j++) {
                int row = wn * 32 + j * 16 + (lane >> 4) * 8 + (lane & 7);
                int col = kk + ((lane >> 3) & 1) * 8;
                unsigned addr = (unsigned)__cvta_generic_to_shared(
                    &Bs[buf][row * GSTR + col]);
                unsigned r0, r1, r2, r3;
                asm volatile(
                    "ldmatrix.sync.aligned.m8n8.x4.shared.b16 {%0,%1,%2,%3}, [%4];\n"
                    : "=r"(r0), "=r"(r1), "=r"(r2), "=r"(r3)
                    : "r"(addr));
                bF[2 * j + 0][0] = r0; bF[2 * j + 0][1] = r1;
                bF[2 * j + 1][0] = r2; bF[2 * j + 1][1] = r3;
            }

#pragma unroll
            for (int i = 0; i < 4; i++)
#pragma unroll
                for (int j = 0; j < 4; j++) {
                    asm volatile(
                        "mma.sync.aligned.m16n8k16.row.col.f32.bf16.bf16.f32 "
                        "{%0,%1,%2,%3}, {%4,%5,%6,%7}, {%8,%9}, {%0,%1,%2,%3};\n"
                        : "+f"(acc[i][j][0]), "+f"(acc[i][j][1]),
                          "+f"(acc[i][j][2]), "+f"(acc[i][j][3])
                        : "r"(aF[i][0]), "r"(aF[i][1]), "r"(aF[i][2]), "r"(aF[i][3]),
                          "r"(bF[j][0]), "r"(bF[j][1]));
                }
        }
        __syncthreads();
    }
#undef ISSUE_TILE

    const int grp = lane >> 2;
    const int qd  = (lane & 3) * 2;
#pragma unroll
    for (int i = 0; i < 4; i++) {
#pragma unroll
        for (int half = 0; half < 2; half++) {
            int m = by * GBM + wm * 64 + i * 16 + grp + half * 8;
            size_t crow = (size_t)m * N;
            size_t grow = (size_t)m * MODC + gate_off;
#pragma unroll
            for (int j = 0; j < 4; j++) {
                int n = bx * GBN + wn * 32 + j * 8 + qd;
                float v0 = acc[i][j][half * 2 + 0];
                float v1 = acc[i][j][half * 2 + 1];
                if (bias) { v0 += bias[n]; v1 += bias[n + 1]; }
                if (EPI == 1) { v0 = gelu_exact(v0); v1 = gelu_exact(v1); }
                if (EPI == 1 || EPI == 3) {
                    bf16* C = (bf16*)Cout;
                    C[crow + n]     = __float2bfloat16(v0);
                    C[crow + n + 1] = __float2bfloat16(v1);
                } else if (EPI == 2) {
                    float* C = (float*)Cout;
                    C[crow + n]     = res[crow + n]     + gate[grow + n]     * v0;
                    C[crow + n + 1] = res[crow + n + 1] + gate[grow + n + 1] * v1;
                } else {
                    float* C = (float*)Cout;
                    C[crow + n]     = v0;
                    C[crow + n + 1] = v1;
                }
            }
        }
    }
}

// ---------------------------------------------------------------------------
// Fast exp on the FMA pipe: e^x = 2^(x*log2e), round-int magic + deg-5 poly.
// Valid for |x*log2e| < 60 (far beyond score range). No MUFU.
// ---------------------------------------------------------------------------
__device__ __forceinline__ float fast_exp(float x)
{
    float y = x * 1.44269504088896f;
    y = fminf(fmaxf(y, -60.0f), 60.0f);
    float t = y + 12582912.0f;               // 1.5 * 2^23 round trick
    float f = y - (t - 12582912.0f);         // f in [-0.5, 0.5]
    int   n = __float_as_int(t) - 0x4B400000;
    float p = 1.33336499e-3f;
    p = fmaf(p, f, 9.61817249e-3f);
    p = fmaf(p, f, 5.55036863e-2f);
    p = fmaf(p, f, 2.40226507e-1f);
    p = fmaf(p, f, 6.93147182e-1f);
    p = fmaf(p, f, 1.0f);
    return p * __int_as_float((n + 127) << 23);
}

__device__ __forceinline__ unsigned pack_bf2(float a, float b)
{
    __nv_bfloat162 t = __floats2bfloat162_rn(a, b);
    return *(unsigned*)&t;
}

// ---------------------------------------------------------------------------
// Tensor-core causal flash attention (no max subtraction; exact softmax math).
// CTA: 128 queries of one (b,h); 4 warps x 32 queries; 64-key K/V tiles.
// qkv bf16 [tok][1536]: q at h*64, k at 512+h*64, v at 1024+h*64.
// ---------------------------------------------------------------------------
#define ASTR 72   // smem row stride (elems): 144B -> 16B bank-group rotation

__global__ void __launch_bounds__(128) attn_tc_kernel(
    const bf16* __restrict__ qkv, bf16* __restrict__ out)
{
    const int b  = blockIdx.z, h = blockIdx.y, qt = blockIdx.x;
    const int tid = threadIdx.x, w = tid >> 5, lane = tid & 31;

    __shared__ bf16 Qs[128 * ASTR];
    __shared__ bf16 Ks[64 * ASTR];
    __shared__ bf16 Vs[64 * ASTR];

    // Stage Q tile (128 x 64)
    for (int idx = tid; idx < 1024; idx += 128) {
        int row = idx >> 3, c8 = (idx & 7) * 8;
        *(uint4*)(&Qs[row * ASTR + c8]) =
            *(const uint4*)(qkv + (size_t)(b * Tt + qt * 128 + row) * QKVC + h * 64 + c8);
    }
    __syncthreads();

    // Q fragments (A operand), 2 m16 tiles x 4 k16 chunks
    unsigned qF[2][4][4];
#pragma unroll
    for (int i = 0; i < 2; i++)
#pragma unroll
        for (int kk = 0; kk < 4; kk++) {
            int row = w * 32 + i * 16 + (lane & 15);
            int col = kk * 16 + (lane >> 4) * 8;
            unsigned addr = (unsigned)__cvta_generic_to_shared(&Qs[row * ASTR + col]);
            asm volatile(
                "ldmatrix.sync.aligned.m8n8.x4.shared.b16 {%0,%1,%2,%3}, [%4];\n"
                : "=r"(qF[i][kk][0]), "=r"(qF[i][kk][1]),
                  "=r"(qF[i][kk][2]), "=r"(qF[i][kk][3])
                : "r"(addr));
        }

    float oAcc[2][8][4];
#pragma unroll
    for (int i = 0; i < 2; i++)
#pragma unroll
        for (int j = 0; j < 8; j++)
#pragma unroll
            for (int r = 0; r < 4; r++) oAcc[i][j][r] = 0.f;
    float lsum[2][2] = {{0.f, 0.f}, {0.f, 0.f}};

    const int qmax  = qt * 128 + w * 32 + 31;
    const int ntile = 2 * (qt + 1);

    for (int kt = 0; kt < ntile; kt++) {
        const int k0 = kt * 64;
        // Stage K/V tiles (64 x 64 each)
        for (int idx = tid; idx < 512; idx += 128) {
            int row = idx >> 3, c8 = (idx & 7) * 8;
            size_t base = (size_t)(b * Tt + k0 + row) * QKVC + h * 64 + c8;
            *(uint4*)(&Ks[row * ASTR + c8]) = *(const uint4*)(qkv + base + 512);
            *(uint4*)(&Vs[row * ASTR + c8]) = *(const uint4*)(qkv + base + 1024);
        }
        __syncthreads();

        if (k0 <= qmax) {
            // S = Q @ K^T  (2 m16 x 8 n8 acc tiles)
            float sAcc[2][8][4];
#pragma unroll
            for (int i = 0; i < 2; i++)
#pragma unroll
                for (int j = 0; j < 8; j++)
#pragma unroll
                    for (int r = 0; r < 4; r++) sAcc[i][j][r] = 0.f;

#pragma unroll
            for (int kk = 0; kk < 4; kk++) {
#pragma unroll
                for (int j2 = 0; j2 < 4; j2++) {
                    int row = j2 * 16 + (lane >> 4) * 8 + (lane & 7);
                    int col = kk * 16 + ((lane >> 3) & 1) * 8;
                    unsigned addr = (unsigned)__cvta_generic_to_shared(
                        &Ks[row * ASTR + col]);
                    unsigned r0, r1, r2, r3;
                    asm volatile(
                        "ldmatrix.sync.aligned.m8n8.x4.shared.b16 {%0,%1,%2,%3}, [%4];\n"
                        : "=r"(r0), "=r"(r1), "=r"(r2), "=r"(r3) : "r"(addr));
#pragma unroll
                    for (int i = 0; i < 2; i++) {
                        asm volatile(
                            "mma.sync.aligned.m16n8k16.row.col.f32.bf16.bf16.f32 "
                            "{%0,%1,%2,%3}, {%4,%5,%6,%7}, {%8,%9}, {%0,%1,%2,%3};\n"
                            : "+f"(sAcc[i][2*j2][0]), "+f"(sAcc[i][2*j2][1]),
                              "+f"(sAcc[i][2*j2][2]), "+f"(sAcc[i][2*j2][3])
                            : "r"(qF[i][kk][0]), "r"(qF[i][kk][1]),
                              "r"(qF[i][kk][2]), "r"(qF[i][kk][3]),
                              "r"(r0), "r"(r1));
                        asm volatile(
                            "mma.sync.aligned.m16n8k16.row.col.f32.bf16.bf16.f32 "
                            "{%0,%1,%2,%3}, {%4,%5,%6,%7}, {%8,%9}, {%0,%1,%2,%3};\n"
                            : "+f"(sAcc[i][2*j2+1][0]), "+f"(sAcc[i][2*j2+1][1]),
                              "+f"(sAcc[i][2*j2+1][2]), "+f"(sAcc[i][2*j2+1][3])
                            : "r"(qF[i][kk][0]), "r"(qF[i][kk][1]),
                              "r"(qF[i][kk][2]), "r"(qF[i][kk][3]),
                              "r"(r2), "r"(r3));
                    }
                }
            }

            // mask + exp + row-sums
            const int qrow0 = qt * 128 + w * 32 + (lane >> 2);
#pragma unroll
            for (int i = 0; i < 2; i++) {
                int q0 = qrow0 + i * 16;
                int q1 = q0 + 8;
#pragma unroll
                for (int j = 0; j < 8; j++) {
                    int kc = k0 + j * 8 + (lane & 3) * 2;
                    float p0 = (kc     <= q0) ? fast_exp(sAcc[i][j][0] * 0.125f) : 0.f;
                    float p1 = (kc + 1 <= q0) ? fast_exp(sAcc[i][j][1] * 0.125f) : 0.f;
                    float p2 = (kc     <= q1) ? fast_exp(sAcc[i][j][2] * 0.125f) : 0.f;
                    float p3 = (kc + 1 <= q1) ? fast_exp(sAcc[i][j][3] * 0.125f) : 0.f;
                    sAcc[i][j][0] = p0; sAcc[i][j][1] = p1;
                    sAcc[i][j][2] = p2; sAcc[i][j][3] = p3;
                    lsum[i][0] += p0 + p1;
                    lsum[i][1] += p2 + p3;
                }
            }

            // O += P @ V  (P fragments repacked from S accumulators)
#pragma unroll
            for (int c = 0; c < 4; c++) {
                unsigned pF[2][4];
#pragma unroll
                for (int i = 0; i < 2; i++) {
                    pF[i][0] = pack_bf2(sAcc[i][2*c  ][0], sAcc[i][2*c  ][1]);
                    pF[i][1] = pack_bf2(sAcc[i][2*c  ][2], sAcc[i][2*c  ][3]);
                    pF[i][2] = pack_bf2(sAcc[i][2*c+1][0], sAcc[i][2*c+1][1]);
                    pF[i][3] = pack_bf2(sAcc[i][2*c+1][2], sAcc[i][2*c+1][3]);
                }
#pragma unroll
                for (int d2 = 0; d2 < 4; d2++) {
                    int g = lane >> 3;
                    int row = c * 16 + (g & 1) * 8 + (lane & 7);
                    int col = d2 * 16 + (g >> 1) * 8;
                    unsigned addr = (unsigned)__cvta_generic_to_shared(
                        &Vs[row * ASTR + col]);
                    unsigned v0, v1, v2, v3;
                    asm volatile(
                        "ldmatrix.sync.aligned.m8n8.x4.trans.shared.b16 {%0,%1,%2,%3}, [%4];\n"
                        : "=r"(v0), "=r"(v1), "=r"(v2), "=r"(v3) : "r"(addr));
#pragma unroll
                    for (int i = 0; i < 2; i++) {
                        asm volatile(
                            "mma.sync.aligned.m16n8k16.row.col.f32.bf16.bf16.f32 "
                            "{%0,%1,%2,%3}, {%4,%5,%6,%7}, {%8,%9}, {%0,%1,%2,%3};\n"
                            : "+f"(oAcc[i][2*d2][0]), "+f"(oAcc[i][2*d2][1]),
                              "+f"(oAcc[i][2*d2][2]), "+f"(oAcc[i][2*d2][3])
                            : "r"(pF[i][0]), "r"(pF[i][1]), "r"(pF[i][2]), "r"(pF[i][3]),
                              "r"(v0), "r"(v1));
                        asm volatile(
                            "mma.sync.aligned.m16n8k16.row.col.f32.bf16.bf16.f32 "
                            "{%0,%1,%2,%3}, {%4,%5,%6,%7}, {%8,%9}, {%0,%1,%2,%3};\n"
                            : "+f"(oAcc[i][2*d2+1][0]), "+f"(oAcc[i][2*d2+1][1]),
                              "+f"(oAcc[i][2*d2+1][2]), "+f"(oAcc[i][2*d2+1][3])
                            : "r"(pF[i][0]), "r"(pF[i][1]), "r"(pF[i][2]), "r"(pF[i][3]),
                              "r"(v2), "r"(v3));
                    }
                }
            }
        }
        __syncthreads();
    }

    // Reduce row-sums across the 4 lanes sharing a row, normalize, store bf16.
#pragma unroll
    for (int i = 0; i < 2; i++) {
#pragma unroll
        for (int hf = 0; hf < 2; hf++) {
            float l = lsum[i][hf];
            l += __shfl_xor_sync(0xffffffffu, l, 1);
            l += __shfl_xor_sync(0xffffffffu, l, 2);
            float inv = 1.0f / l;
            int qg = qt * 128 + w * 32 + i * 16 + (lane >> 2) + hf * 8;
            bf16* orow = out + (size_t)(b * Tt + qg) * DIMd + h * DHEAD;
#pragma unroll
            for (int j = 0; j < 8; j++) {
                int d = j * 8 + (lane & 3) * 2;
                *(unsigned*)(orow + d) =
                    pack_bf2(oAcc[i][j][hf * 2] * inv, oAcc[i][j][hf * 2 + 1] * inv);
            }
        }
    }
}

// ---------------------------------------------------------------------------
// Launch
// Inputs: 0:x 1:action_emb 2:causal_mask 3:Wqkv 4:Wout 5:bout
//         6:W1 7:b1 8:W2 9:b2 10:Wmod 11:bmod
// ---------------------------------------------------------------------------
extern "C" void kernel_launch(void* const* d_in, const int* in_sizes, int n_in,
                              void* d_out, int out_size)
{
    const float* x    = (const float*)d_in[0];
    const float* aemb = (const float*)d_in[1];
    const float* Wqkv = (const float*)d_in[3];
    const float* Wout = (const float*)d_in[4];
    const float* bout = (const float*)d_in[5];
    const float* W1   = (const float*)d_in[6];
    const float* b1   = (const float*)d_in[7];
    const float* W2   = (const float*)d_in[8];
    const float* b2   = (const float*)d_in[9];
    const float* Wmod = (const float*)d_in[10];
    const float* bmod = (const float*)d_in[11];
    float* out = (float*)d_out;

    float *mod_p, *x1_p;
    bf16 *silu_p, *h_p, *qkv_p, *attn_p, *mlp_p;
    bf16 *wqkv_p, *wout_p, *w1_p, *w2_p, *wmod_p;
    cudaGetSymbolAddress((void**)&mod_p,  g_mod);
    cudaGetSymbolAddress((void**)&x1_p,   g_x1);
    cudaGetSymbolAddress((void**)&silu_p, g_silu_bf);
    cudaGetSymbolAddress((void**)&h_p,    g_h_bf);
    cudaGetSymbolAddress((void**)&qkv_p,  g_qkv_bf);
    cudaGetSymbolAddress((void**)&attn_p, g_attn_bf);
    cudaGetSymbolAddress((void**)&mlp_p,  g_mlp_bf);
    cudaGetSymbolAddress((void**)&wqkv_p, g_Wqkv_bf);
    cudaGetSymbolAddress((void**)&wout_p, g_Wout_bf);
    cudaGetSymbolAddress((void**)&w1_p,   g_W1_bf);
    cudaGetSymbolAddress((void**)&w2_p,   g_W2_bf);
    cudaGetSymbolAddress((void**)&wmod_p, g_Wmod_bf);

    // Weight conversions
    f2bf_kernel<<<(QKVC*DIMd + 255)/256, 256>>>(Wqkv, wqkv_p, QKVC*DIMd);
    f2bf_kernel<<<(DIMd*DIMd + 255)/256, 256>>>(Wout, wout_p, DIMd*DIMd);
    f2bf_kernel<<<(MLPD*DIMd + 255)/256, 256>>>(W1, w1_p, MLPD*DIMd);
    f2bf_kernel<<<(DIMd*MLPD + 255)/256, 256>>>(W2, w2_p, DIMd*MLPD);
    f2bf_kernel<<<(MODC*ADIM + 255)/256, 256>>>(Wmod, wmod_p, MODC*ADIM);

    // 1) silu(action_emb) -> bf16
    silu_kernel<<<(NTOK * ADIM + 255) / 256, 256>>>(aemb, silu_p, NTOK * ADIM);

    // 2) mod = silu_a @ Wmod^T + bmod  (fp32 out)
    mma_gemm<0><<<dim3(MODC / GBN, NTOK / GBM), 256>>>(
        silu_p, wmod_p, bmod, nullptr, nullptr, 0, mod_p, NTOK, MODC, ADIM);

    // 3) h = LN(x)*(1+scale1)+shift1 -> bf16
    lnmod_kernel<<<NTOK, 128>>>(x, mod_p, 0, DIMd, h_p);

    // 4) qkv = h @ Wqkv^T -> bf16
    mma_gemm<3><<<dim3(QKVC / GBN, NTOK / GBM), 256>>>(
        h_p, wqkv_p, nullptr, nullptr, nullptr, 0, qkv_p, NTOK, QKVC, DIMd);

    // 5) tensor-core causal attention -> bf16
    attn_tc_kernel<<<dim3(Tt / 128, NHEAD, Bb), 128>>>(qkv_p, attn_p);

    // 6) x1 = x + gate1 * (attn @ Wout^T + bout)  (fp32 out)
    mma_gemm<2><<<dim3(DIMd / GBN, NTOK / GBM), 256>>>(
        attn_p, wout_p, bout, x, mod_p, 2 * DIMd, x1_p, NTOK, DIMd, DIMd);

    // 7) h = LN(x1)*(1+scale2)+shift2 -> bf16
    lnmod_kernel<<<NTOK, 128>>>(x1_p, mod_p, 3 * DIMd, 4 * DIMd, h_p);

    // 8) mlp = gelu(h @ W1^T + b1) -> bf16
    mma_gemm<1><<<dim3(MLPD / GBN, NTOK / GBM), 256>>>(
        h_p, w1_p, b1, nullptr, nullptr, 0, mlp_p, NTOK, MLPD, DIMd);

    // 9) out = x1 + gate2 * (mlp @ W2^T + b2)  (fp32 out)
    mma_gemm<2><<<dim3(DIMd / GBN, NTOK / GBM), 256>>>(
        mlp_p, w2_p, b2, x1_p, mod_p, 5 * DIMd, out, NTOK, DIMd, MLPD);
}

// round 6
// speedup vs baseline: 5.4338x; 1.1451x over previous
#include <cuda_runtime.h>
#include <cuda_bf16.h>
#include <math.h>

// Problem constants
#define Bb     4
#define Tt     2048
#define DIMd   512
#define NHEAD  8
#define DHEAD  64
#define MLPD   2048
#define ADIM   256
#define NTOK   (Bb * Tt)
#define MODC   (6 * DIMd)
#define QKVC   (3 * DIMd)

typedef __nv_bfloat16 bf16;

// ---------------------------------------------------------------------------
// Scratch (static device globals; allocation-free per harness rules)
// ---------------------------------------------------------------------------
__device__ __align__(256) float g_x1 [NTOK * DIMd];          // fp32 residual

__device__ __align__(256) bf16 g_mod_bf [(size_t)NTOK * MODC];
__device__ __align__(256) bf16 g_silu_bf[NTOK * ADIM];
__device__ __align__(256) bf16 g_h_bf   [NTOK * DIMd];
__device__ __align__(256) bf16 g_qkv_bf [(size_t)NTOK * QKVC];
__device__ __align__(256) bf16 g_attn_bf[NTOK * DIMd];
__device__ __align__(256) bf16 g_mlp_bf [(size_t)NTOK * MLPD];

__device__ __align__(256) bf16 g_Wqkv_bf[QKVC * DIMd];
__device__ __align__(256) bf16 g_Wout_bf[DIMd * DIMd];
__device__ __align__(256) bf16 g_W1_bf  [MLPD * DIMd];
__device__ __align__(256) bf16 g_W2_bf  [DIMd * MLPD];
__device__ __align__(256) bf16 g_Wmod_bf[MODC * ADIM];

// ---------------------------------------------------------------------------
// Helpers
// ---------------------------------------------------------------------------
__device__ __forceinline__ unsigned smem_u32(const void* p)
{
    return (unsigned)__cvta_generic_to_shared(p);
}
__device__ __forceinline__ unsigned pack_bf2(float a, float b)
{
    __nv_bfloat162 t = __floats2bfloat162_rn(a, b);
    return *(unsigned*)&t;
}
__device__ __forceinline__ float gelu_exact(float v)
{
    return 0.5f * v * (1.0f + erff(v * 0.70710678118654752f));
}
__device__ __forceinline__ float fast_exp(float x)
{
    float y = x * 1.44269504088896f;
    y = fminf(fmaxf(y, -60.0f), 60.0f);
    float t = y + 12582912.0f;
    float f = y - (t - 12582912.0f);
    int   n = __float_as_int(t) - 0x4B400000;
    float p = 1.33336499e-3f;
    p = fmaf(p, f, 9.61817249e-3f);
    p = fmaf(p, f, 5.55036863e-2f);
    p = fmaf(p, f, 2.40226507e-1f);
    p = fmaf(p, f, 6.93147182e-1f);
    p = fmaf(p, f, 1.0f);
    return p * __int_as_float((n + 127) << 23);
}

// ---------------------------------------------------------------------------
// Elementwise kernels
// ---------------------------------------------------------------------------
__global__ void f2bf_kernel(const float* __restrict__ in, bf16* __restrict__ out, int n)
{
    int i = blockIdx.x * blockDim.x + threadIdx.x;
    if (i < n) out[i] = __float2bfloat16(in[i]);
}

__global__ void silu_kernel(const float* __restrict__ a, bf16* __restrict__ out, int n)
{
    int i = blockIdx.x * blockDim.x + threadIdx.x;
    if (i < n) {
        float v = a[i];
        out[i] = __float2bfloat16(v / (1.0f + __expf(-v)));
    }
}

// Fused LayerNorm + AdaLN modulation -> bf16 (mod is bf16 now)
__global__ void lnmod_kernel(const float* __restrict__ x,
                             const bf16* __restrict__ mod,
                             int shift_off, int scale_off,
                             bf16* __restrict__ out)
{
    int row = blockIdx.x;
    int t   = threadIdx.x;
    const float* xr = x + (size_t)row * DIMd;

    float v[4];
    float s1 = 0.f, s2 = 0.f;
#pragma unroll
    for (int j = 0; j < 4; j++) {
        float z = xr[t + j * 128];
        v[j] = z; s1 += z; s2 += z * z;
    }
#pragma unroll
    for (int off = 16; off; off >>= 1) {
        s1 += __shfl_xor_sync(0xffffffffu, s1, off);
        s2 += __shfl_xor_sync(0xffffffffu, s2, off);
    }
    __shared__ float r1[4], r2[4];
    int w = t >> 5;
    if ((t & 31) == 0) { r1[w] = s1; r2[w] = s2; }
    __syncthreads();
    s1 = r1[0] + r1[1] + r1[2] + r1[3];
    s2 = r2[0] + r2[1] + r2[2] + r2[3];

    float mu   = s1 * (1.0f / DIMd);
    float var  = s2 * (1.0f / DIMd) - mu * mu;
    float rstd = rsqrtf(var + 1e-5f);

    const bf16* mrow = mod + (size_t)row * MODC;
    bf16* orow = out + (size_t)row * DIMd;
#pragma unroll
    for (int j = 0; j < 4; j++) {
        int c = t + j * 128;
        float sc = __bfloat162float(mrow[scale_off + c]);
        float sh = __bfloat162float(mrow[shift_off + c]);
        orow[c] = __float2bfloat16((v[j] - mu) * rstd * (1.0f + sc) + sh);
    }
}

// ---------------------------------------------------------------------------
// bf16 tensor-core GEMM: C[M,N] = A[M,K] @ B[N,K]^T (+bias)(+epilogue)
// 128x128x32 tiles, 256 thr (8 warps, 2x4 grid, 64x32 warp tiles),
// 3-stage cp.async circular pipeline (ONE sync per tile),
// register double-buffered ldmatrix fragments.
// EPI: 1 = GELU(acc+bias) bf16 out
//      2 = res + gate*(acc+bias) fp32 out (gate bf16)
//      3 = acc(+bias) bf16 out
// ---------------------------------------------------------------------------
#define GBM 128
#define GBN 128
#define GBK 32
#define GSTR (GBK + 8)
#define STAGES 3
#define STAGE_ELEMS (2 * GBM * GSTR)          // A tile + B tile per stage
#define GEMM_SMEM (STAGES * STAGE_ELEMS * 2)  // bytes = 61440

__device__ __forceinline__ void g2s_tile(
    const bf16* __restrict__ Ag, const bf16* __restrict__ Bg,
    int K, int kt, bf16* smemBuf, int lr, int lc)
{
    bf16* As = smemBuf + (kt % STAGES) * STAGE_ELEMS;
    bf16* Bs = As + GBM * GSTR;
    const int k0 = kt * GBK;
#pragma unroll
    for (int p = 0; p < 2; p++) {
        int row = lr + p * 64;
        unsigned sA = smem_u32(&As[row * GSTR + lc]);
        asm volatile("cp.async.cg.shared.global [%0], [%1], 16;\n"
                     :: "r"(sA), "l"(Ag + (size_t)row * K + k0 + lc));
        unsigned sB = smem_u32(&Bs[row * GSTR + lc]);
        asm volatile("cp.async.cg.shared.global [%0], [%1], 16;\n"
                     :: "r"(sB), "l"(Bg + (size_t)row * K + k0 + lc));
    }
    asm volatile("cp.async.commit_group;\n" ::: "memory");
}

__device__ __forceinline__ void load_frags(
    const bf16* As, const bf16* Bs, int ks, int wm, int wn, int lane,
    unsigned aF[4][4], unsigned bF[4][2])
{
    const int kk = ks * 16;
#pragma unroll
    for (int i = 0; i < 4; i++) {
        int row = wm * 64 + i * 16 + (lane & 15);
        int col = kk + (lane >> 4) * 8;
        unsigned addr = smem_u32(&As[row * GSTR + col]);
        asm volatile(
            "ldmatrix.sync.aligned.m8n8.x4.shared.b16 {%0,%1,%2,%3}, [%4];\n"
            : "=r"(aF[i][0]), "=r"(aF[i][1]), "=r"(aF[i][2]), "=r"(aF[i][3])
            : "r"(addr));
    }
#pragma unroll
    for (int j = 0; j < 2; j++) {
        int row = wn * 32 + j * 16 + (lane >> 4) * 8 + (lane & 7);
        int col = kk + ((lane >> 3) & 1) * 8;
        unsigned addr = smem_u32(&Bs[row * GSTR + col]);
        unsigned r0, r1, r2, r3;
        asm volatile(
            "ldmatrix.sync.aligned.m8n8.x4.shared.b16 {%0,%1,%2,%3}, [%4];\n"
            : "=r"(r0), "=r"(r1), "=r"(r2), "=r"(r3)
            : "r"(addr));
        bF[2 * j + 0][0] = r0; bF[2 * j + 0][1] = r1;
        bF[2 * j + 1][0] = r2; bF[2 * j + 1][1] = r3;
    }
}

template <int EPI>
__global__ void __launch_bounds__(256) mma_gemm(
    const bf16* __restrict__ A,
    const bf16* __restrict__ Bw,
    const float* __restrict__ bias,
    const float* __restrict__ res,
    const bf16* __restrict__ gate, int gate_off,
    void* __restrict__ Cout,
    int M, int N, int K)
{
    extern __shared__ bf16 smemBuf[];

    const int tid  = threadIdx.x;
    const int bx   = blockIdx.x, by = blockIdx.y;
    const int wid  = tid >> 5, lane = tid & 31;
    const int wm   = wid & 1;
    const int wn   = wid >> 1;

    const int lr = tid >> 2;
    const int lc = (tid & 3) * 8;
    const bf16* Ag = A  + (size_t)(by * GBM) * K;
    const bf16* Bg = Bw + (size_t)(bx * GBN) * K;

    float acc[4][4][4];
#pragma unroll
    for (int i = 0; i < 4; i++)
#pragma unroll
        for (int j = 0; j < 4; j++)
#pragma unroll
            for (int r = 0; r < 4; r++) acc[i][j][r] = 0.f;

    const int KT = K / GBK;

    // Prologue: stages 0 and 1 in flight
    g2s_tile(Ag, Bg, K, 0, smemBuf, lr, lc);
    g2s_tile(Ag, Bg, K, 1, smemBuf, lr, lc);

    for (int kt = 0; kt < KT; kt++) {
        if (kt == KT - 1)
            asm volatile("cp.async.wait_group 0;" ::: "memory");
        else
            asm volatile("cp.async.wait_group 1;" ::: "memory");
        __syncthreads();

        // Refill the stage that held tile kt-1 (fully consumed last iteration).
        if (kt + 2 < KT) g2s_tile(Ag, Bg, K, kt + 2, smemBuf, lr, lc);

        const bf16* As = smemBuf + (kt % STAGES) * STAGE_ELEMS;
        const bf16* Bs = As + GBM * GSTR;

        unsigned aF[2][4][4], bF[2][4][2];
        load_frags(As, Bs, 0, wm, wn, lane, aF[0], bF[0]);

#pragma unroll
        for (int ks = 0; ks < 2; ks++) {
            if (ks == 0) load_frags(As, Bs, 1, wm, wn, lane, aF[1], bF[1]);
#pragma unroll
            for (int i = 0; i < 4; i++)
#pragma unroll
                for (int j = 0; j < 4; j++) {
                    asm volatile(
                        "mma.sync.aligned.m16n8k16.row.col.f32.bf16.bf16.f32 "
                        "{%0,%1,%2,%3}, {%4,%5,%6,%7}, {%8,%9}, {%0,%1,%2,%3};\n"
                        : "+f"(acc[i][j][0]), "+f"(acc[i][j][1]),
                          "+f"(acc[i][j][2]), "+f"(acc[i][j][3])
                        : "r"(aF[ks][i][0]), "r"(aF[ks][i][1]),
                          "r"(aF[ks][i][2]), "r"(aF[ks][i][3]),
                          "r"(bF[ks][j][0]), "r"(bF[ks][j][1]));
                }
        }
    }

    // Epilogue. acc: c0,c1 = (row=lane/4, col=2*(lane%4)+{0,1}); c2,c3 = row+8
    const int grp = lane >> 2;
    const int qd  = (lane & 3) * 2;
#pragma unroll
    for (int i = 0; i < 4; i++) {
#pragma unroll
        for (int half = 0; half < 2; half++) {
            int m = by * GBM + wm * 64 + i * 16 + grp + half * 8;
            size_t crow = (size_t)m * N;
            size_t grow = (size_t)m * MODC + gate_off;
#pragma unroll
            for (int j = 0; j < 4; j++) {
                int n = bx * GBN + wn * 32 + j * 8 + qd;
                float v0 = acc[i][j][half * 2 + 0];
                float v1 = acc[i][j][half * 2 + 1];
                if (bias) { v0 += bias[n]; v1 += bias[n + 1]; }
                if (EPI == 1) { v0 = gelu_exact(v0); v1 = gelu_exact(v1); }
                if (EPI == 1 || EPI == 3) {
                    bf16* C = (bf16*)Cout;
                    *(unsigned*)(C + crow + n) = pack_bf2(v0, v1);
                } else if (EPI == 2) {
                    float* C = (float*)Cout;
                    float g0 = __bfloat162float(gate[grow + n]);
                    float g1 = __bfloat162float(gate[grow + n + 1]);
                    C[crow + n]     = res[crow + n]     + g0 * v0;
                    C[crow + n + 1] = res[crow + n + 1] + g1 * v1;
                }
            }
        }
    }
}

// ---------------------------------------------------------------------------
// Tensor-core causal flash attention (unchanged from round 4)
// ---------------------------------------------------------------------------
#define ASTR 72

__global__ void __launch_bounds__(128) attn_tc_kernel(
    const bf16* __restrict__ qkv, bf16* __restrict__ out)
{
    const int b  = blockIdx.z, h = blockIdx.y, qt = blockIdx.x;
    const int tid = threadIdx.x, w = tid >> 5, lane = tid & 31;

    __shared__ bf16 Qs[128 * ASTR];
    __shared__ bf16 Ks[64 * ASTR];
    __shared__ bf16 Vs[64 * ASTR];

    for (int idx = tid; idx < 1024; idx += 128) {
        int row = idx >> 3, c8 = (idx & 7) * 8;
        *(uint4*)(&Qs[row * ASTR + c8]) =
            *(const uint4*)(qkv + (size_t)(b * Tt + qt * 128 + row) * QKVC + h * 64 + c8);
    }
    __syncthreads();

    unsigned qF[2][4][4];
#pragma unroll
    for (int i = 0; i < 2; i++)
#pragma unroll
        for (int kk = 0; kk < 4; kk++) {
            int row = w * 32 + i * 16 + (lane & 15);
            int col = kk * 16 + (lane >> 4) * 8;
            unsigned addr = smem_u32(&Qs[row * ASTR + col]);
            asm volatile(
                "ldmatrix.sync.aligned.m8n8.x4.shared.b16 {%0,%1,%2,%3}, [%4];\n"
                : "=r"(qF[i][kk][0]), "=r"(qF[i][kk][1]),
                  "=r"(qF[i][kk][2]), "=r"(qF[i][kk][3])
                : "r"(addr));
        }

    float oAcc[2][8][4];
#pragma unroll
    for (int i = 0; i < 2; i++)
#pragma unroll
        for (int j = 0; j < 8; j++)
#pragma unroll
            for (int r = 0; r < 4; r++) oAcc[i][j][r] = 0.f;
    float lsum[2][2] = {{0.f, 0.f}, {0.f, 0.f}};

    const int qmax  = qt * 128 + w * 32 + 31;
    const int ntile = 2 * (qt + 1);

    for (int kt = 0; kt < ntile; kt++) {
        const int k0 = kt * 64;
        for (int idx = tid; idx < 512; idx += 128) {
            int row = idx >> 3, c8 = (idx & 7) * 8;
            size_t base = (size_t)(b * Tt + k0 + row) * QKVC + h * 64 + c8;
            *(uint4*)(&Ks[row * ASTR + c8]) = *(const uint4*)(qkv + base + 512);
            *(uint4*)(&Vs[row * ASTR + c8]) = *(const uint4*)(qkv + base + 1024);
        }
        __syncthreads();

        if (k0 <= qmax) {
            float sAcc[2][8][4];
#pragma unroll
            for (int i = 0; i < 2; i++)
#pragma unroll
                for (int j = 0; j < 8; j++)
#pragma unroll
                    for (int r = 0; r < 4; r++) sAcc[i][j][r] = 0.f;

#pragma unroll
            for (int kk = 0; kk < 4; kk++) {
#pragma unroll
                for (int j2 = 0; j2 < 4; j2++) {
                    int row = j2 * 16 + (lane >> 4) * 8 + (lane & 7);
                    int col = kk * 16 + ((lane >> 3) & 1) * 8;
                    unsigned addr = smem_u32(&Ks[row * ASTR + col]);
                    unsigned r0, r1, r2, r3;
                    asm volatile(
                        "ldmatrix.sync.aligned.m8n8.x4.shared.b16 {%0,%1,%2,%3}, [%4];\n"
                        : "=r"(r0), "=r"(r1), "=r"(r2), "=r"(r3) : "r"(addr));
#pragma unroll
                    for (int i = 0; i < 2; i++) {
                        asm volatile(
                            "mma.sync.aligned.m16n8k16.row.col.f32.bf16.bf16.f32 "
                            "{%0,%1,%2,%3}, {%4,%5,%6,%7}, {%8,%9}, {%0,%1,%2,%3};\n"
                            : "+f"(sAcc[i][2*j2][0]), "+f"(sAcc[i][2*j2][1]),
                              "+f"(sAcc[i][2*j2][2]), "+f"(sAcc[i][2*j2][3])
                            : "r"(qF[i][kk][0]), "r"(qF[i][kk][1]),
                              "r"(qF[i][kk][2]), "r"(qF[i][kk][3]),
                              "r"(r0), "r"(r1));
                        asm volatile(
                            "mma.sync.aligned.m16n8k16.row.col.f32.bf16.bf16.f32 "
                            "{%0,%1,%2,%3}, {%4,%5,%6,%7}, {%8,%9}, {%0,%1,%2,%3};\n"
                            : "+f"(sAcc[i][2*j2+1][0]), "+f"(sAcc[i][2*j2+1][1]),
                              "+f"(sAcc[i][2*j2+1][2]), "+f"(sAcc[i][2*j2+1][3])
                            : "r"(qF[i][kk][0]), "r"(qF[i][kk][1]),
                              "r"(qF[i][kk][2]), "r"(qF[i][kk][3]),
                              "r"(r2), "r"(r3));
                    }
                }
            }

            const int qrow0 = qt * 128 + w * 32 + (lane >> 2);
#pragma unroll
            for (int i = 0; i < 2; i++) {
                int q0 = qrow0 + i * 16;
                int q1 = q0 + 8;
#pragma unroll
                for (int j = 0; j < 8; j++) {
                    int kc = k0 + j * 8 + (lane & 3) * 2;
                    float p0 = (kc     <= q0) ? fast_exp(sAcc[i][j][0] * 0.125f) : 0.f;
                    float p1 = (kc + 1 <= q0) ? fast_exp(sAcc[i][j][1] * 0.125f) : 0.f;
                    float p2 = (kc     <= q1) ? fast_exp(sAcc[i][j][2] * 0.125f) : 0.f;
                    float p3 = (kc + 1 <= q1) ? fast_exp(sAcc[i][j][3] * 0.125f) : 0.f;
                    sAcc[i][j][0] = p0; sAcc[i][j][1] = p1;
                    sAcc[i][j][2] = p2; sAcc[i][j][3] = p3;
                    lsum[i][0] += p0 + p1;
                    lsum[i][1] += p2 + p3;
                }
            }

#pragma unroll
            for (int c = 0; c < 4; c++) {
                unsigned pF[2][4];
#pragma unroll
                for (int i = 0; i < 2; i++) {
                    pF[i][0] = pack_bf2(sAcc[i][2*c  ][0], sAcc[i][2*c  ][1]);
                    pF[i][1] = pack_bf2(sAcc[i][2*c  ][2], sAcc[i][2*c  ][3]);
                    pF[i][2] = pack_bf2(sAcc[i][2*c+1][0], sAcc[i][2*c+1][1]);
                    pF[i][3] = pack_bf2(sAcc[i][2*c+1][2], sAcc[i][2*c+1][3]);
                }
#pragma unroll
                for (int d2 = 0; d2 < 4; d2++) {
                    int g = lane >> 3;
                    int row = c * 16 + (g & 1) * 8 + (lane & 7);
                    int col = d2 * 16 + (g >> 1) * 8;
                    unsigned addr = smem_u32(&Vs[row * ASTR + col]);
                    unsigned v0, v1, v2, v3;
                    asm volatile(
                        "ldmatrix.sync.aligned.m8n8.x4.trans.shared.b16 {%0,%1,%2,%3}, [%4];\n"
                        : "=r"(v0), "=r"(v1), "=r"(v2), "=r"(v3) : "r"(addr));
#pragma unroll
                    for (int i = 0; i < 2; i++) {
                        asm volatile(
                            "mma.sync.aligned.m16n8k16.row.col.f32.bf16.bf16.f32 "
                            "{%0,%1,%2,%3}, {%4,%5,%6,%7}, {%8,%9}, {%0,%1,%2,%3};\n"
                            : "+f"(oAcc[i][2*d2][0]), "+f"(oAcc[i][2*d2][1]),
                              "+f"(oAcc[i][2*d2][2]), "+f"(oAcc[i][2*d2][3])
                            : "r"(pF[i][0]), "r"(pF[i][1]), "r"(pF[i][2]), "r"(pF[i][3]),
                              "r"(v0), "r"(v1));
                        asm volatile(
                            "mma.sync.aligned.m16n8k16.row.col.f32.bf16.bf16.f32 "
                            "{%0,%1,%2,%3}, {%4,%5,%6,%7}, {%8,%9}, {%0,%1,%2,%3};\n"
                            : "+f"(oAcc[i][2*d2+1][0]), "+f"(oAcc[i][2*d2+1][1]),
                              "+f"(oAcc[i][2*d2+1][2]), "+f"(oAcc[i][2*d2+1][3])
                            : "r"(pF[i][0]), "r"(pF[i][1]), "r"(pF[i][2]), "r"(pF[i][3]),
                              "r"(v2), "r"(v3));
                    }
                }
            }
        }
        __syncthreads();
    }

#pragma unroll
    for (int i = 0; i < 2; i++) {
#pragma unroll
        for (int hf = 0; hf < 2; hf++) {
            float l = lsum[i][hf];
            l += __shfl_xor_sync(0xffffffffu, l, 1);
            l += __shfl_xor_sync(0xffffffffu, l, 2);
            float inv = 1.0f / l;
            int qg = qt * 128 + w * 32 + i * 16 + (lane >> 2) + hf * 8;
            bf16* orow = out + (size_t)(b * Tt + qg) * DIMd + h * DHEAD;
#pragma unroll
            for (int j = 0; j < 8; j++) {
                int d = j * 8 + (lane & 3) * 2;
                *(unsigned*)(orow + d) =
                    pack_bf2(oAcc[i][j][hf * 2] * inv, oAcc[i][j][hf * 2 + 1] * inv);
            }
        }
    }
}

// ---------------------------------------------------------------------------
// Launch
// Inputs: 0:x 1:action_emb 2:causal_mask 3:Wqkv 4:Wout 5:bout
//         6:W1 7:b1 8:W2 9:b2 10:Wmod 11:bmod
// ---------------------------------------------------------------------------
extern "C" void kernel_launch(void* const* d_in, const int* in_sizes, int n_in,
                              void* d_out, int out_size)
{
    const float* x    = (const float*)d_in[0];
    const float* aemb = (const float*)d_in[1];
    const float* Wqkv = (const float*)d_in[3];
    const float* Wout = (const float*)d_in[4];
    const float* bout = (const float*)d_in[5];
    const float* W1   = (const float*)d_in[6];
    const float* b1   = (const float*)d_in[7];
    const float* W2   = (const float*)d_in[8];
    const float* b2   = (const float*)d_in[9];
    const float* Wmod = (const float*)d_in[10];
    const float* bmod = (const float*)d_in[11];
    float* out = (float*)d_out;

    float *x1_p;
    bf16 *mod_p, *silu_p, *h_p, *qkv_p, *attn_p, *mlp_p;
    bf16 *wqkv_p, *wout_p, *w1_p, *w2_p, *wmod_p;
    cudaGetSymbolAddress((void**)&x1_p,   g_x1);
    cudaGetSymbolAddress((void**)&mod_p,  g_mod_bf);
    cudaGetSymbolAddress((void**)&silu_p, g_silu_bf);
    cudaGetSymbolAddress((void**)&h_p,    g_h_bf);
    cudaGetSymbolAddress((void**)&qkv_p,  g_qkv_bf);
    cudaGetSymbolAddress((void**)&attn_p, g_attn_bf);
    cudaGetSymbolAddress((void**)&mlp_p,  g_mlp_bf);
    cudaGetSymbolAddress((void**)&wqkv_p, g_Wqkv_bf);
    cudaGetSymbolAddress((void**)&wout_p, g_Wout_bf);
    cudaGetSymbolAddress((void**)&w1_p,   g_W1_bf);
    cudaGetSymbolAddress((void**)&w2_p,   g_W2_bf);
    cudaGetSymbolAddress((void**)&wmod_p, g_Wmod_bf);

    cudaFuncSetAttribute(mma_gemm<1>, cudaFuncAttributeMaxDynamicSharedMemorySize, GEMM_SMEM);
    cudaFuncSetAttribute(mma_gemm<2>, cudaFuncAttributeMaxDynamicSharedMemorySize, GEMM_SMEM);
    cudaFuncSetAttribute(mma_gemm<3>, cudaFuncAttributeMaxDynamicSharedMemorySize, GEMM_SMEM);

    // Weight conversions
    f2bf_kernel<<<(QKVC*DIMd + 255)/256, 256>>>(Wqkv, wqkv_p, QKVC*DIMd);
    f2bf_kernel<<<(DIMd*DIMd + 255)/256, 256>>>(Wout, wout_p, DIMd*DIMd);
    f2bf_kernel<<<(MLPD*DIMd + 255)/256, 256>>>(W1, w1_p, MLPD*DIMd);
    f2bf_kernel<<<(DIMd*MLPD + 255)/256, 256>>>(W2, w2_p, DIMd*MLPD);
    f2bf_kernel<<<(MODC*ADIM + 255)/256, 256>>>(Wmod, wmod_p, MODC*ADIM);

    // 1) silu(action_emb) -> bf16
    silu_kernel<<<(NTOK * ADIM + 255) / 256, 256>>>(aemb, silu_p, NTOK * ADIM);

    // 2) mod = silu_a @ Wmod^T + bmod -> bf16
    mma_gemm<3><<<dim3(MODC / GBN, NTOK / GBM), 256, GEMM_SMEM>>>(
        silu_p, wmod_p, bmod, nullptr, nullptr, 0, mod_p, NTOK, MODC, ADIM);

    // 3) h = LN(x)*(1+scale1)+shift1 -> bf16
    lnmod_kernel<<<NTOK, 128>>>(x, mod_p, 0, DIMd, h_p);

    // 4) qkv = h @ Wqkv^T -> bf16
    mma_gemm<3><<<dim3(QKVC / GBN, NTOK / GBM), 256, GEMM_SMEM>>>(
        h_p, wqkv_p, nullptr, nullptr, nullptr, 0, qkv_p, NTOK, QKVC, DIMd);

    // 5) tensor-core causal attention -> bf16
    attn_tc_kernel<<<dim3(Tt / 128, NHEAD, Bb), 128>>>(qkv_p, attn_p);

    // 6) x1 = x + gate1 * (attn @ Wout^T + bout)  fp32 out
    mma_gemm<2><<<dim3(DIMd / GBN, NTOK / GBM), 256, GEMM_SMEM>>>(
        attn_p, wout_p, bout, x, mod_p, 2 * DIMd, x1_p, NTOK, DIMd, DIMd);

    // 7) h = LN(x1)*(1+scale2)+shift2 -> bf16
    lnmod_kernel<<<NTOK, 128>>>(x1_p, mod_p, 3 * DIMd, 4 * DIMd, h_p);

    // 8) mlp = gelu(h @ W1^T + b1) -> bf16
    mma_gemm<1><<<dim3(MLPD / GBN, NTOK / GBM), 256, GEMM_SMEM>>>(
        h_p, w1_p, b1, nullptr, nullptr, 0, mlp_p, NTOK, MLPD, DIMd);

    // 9) out = x1 + gate2 * (mlp @ W2^T + b2)  fp32 out
    mma_gemm<2><<<dim3(DIMd / GBN, NTOK / GBM), 256, GEMM_SMEM>>>(
        mlp_p, w2_p, b2, x1_p, mod_p, 5 * DIMd, out, NTOK, DIMd, MLPD);
}

// round 8
// speedup vs baseline: 6.1118x; 1.1248x over previous
#include <cuda_runtime.h>
#include <cuda_bf16.h>
#include <math.h>

// Problem constants
#define Bb     4
#define Tt     2048
#define DIMd   512
#define NHEAD  8
#define DHEAD  64
#define MLPD   2048
#define ADIM   256
#define NTOK   (Bb * Tt)
#define MODC   (6 * DIMd)
#define QKVC   (3 * DIMd)

typedef __nv_bfloat16 bf16;

// ---------------------------------------------------------------------------
// Scratch (static device globals; allocation-free per harness rules)
// ---------------------------------------------------------------------------
__device__ __align__(256) float g_x1 [NTOK * DIMd];          // fp32 residual

__device__ __align__(256) bf16 g_mod_bf [(size_t)NTOK * MODC];
__device__ __align__(256) bf16 g_silu_bf[NTOK * ADIM];
__device__ __align__(256) bf16 g_h_bf   [NTOK * DIMd];
__device__ __align__(256) bf16 g_qkv_bf [(size_t)NTOK * QKVC];
__device__ __align__(256) bf16 g_attn_bf[NTOK * DIMd];
__device__ __align__(256) bf16 g_mlp_bf [(size_t)NTOK * MLPD];

__device__ __align__(256) bf16 g_Wqkv_bf[QKVC * DIMd];
__device__ __align__(256) bf16 g_Wout_bf[DIMd * DIMd];
__device__ __align__(256) bf16 g_W1_bf  [MLPD * DIMd];
__device__ __align__(256) bf16 g_W2_bf  [DIMd * MLPD];
__device__ __align__(256) bf16 g_Wmod_bf[MODC * ADIM];

// ---------------------------------------------------------------------------
// Helpers
// ---------------------------------------------------------------------------
__device__ __forceinline__ unsigned smem_u32(const void* p)
{
    return (unsigned)__cvta_generic_to_shared(p);
}
__device__ __forceinline__ unsigned pack_bf2(float a, float b)
{
    __nv_bfloat162 t = __floats2bfloat162_rn(a, b);
    return *(unsigned*)&t;
}
__device__ __forceinline__ float gelu_exact(float v)
{
    return 0.5f * v * (1.0f + erff(v * 0.70710678118654752f));
}
__device__ __forceinline__ float fast_exp(float x)
{
    float y = x * 1.44269504088896f;
    y = fminf(fmaxf(y, -60.0f), 60.0f);
    float t = y + 12582912.0f;
    float f = y - (t - 12582912.0f);
    int   n = __float_as_int(t) - 0x4B400000;
    float p = 1.33336499e-3f;
    p = fmaf(p, f, 9.61817249e-3f);
    p = fmaf(p, f, 5.55036863e-2f);
    p = fmaf(p, f, 2.40226507e-1f);
    p = fmaf(p, f, 6.93147182e-1f);
    p = fmaf(p, f, 1.0f);
    return p * __int_as_float((n + 127) << 23);
}

// ---------------------------------------------------------------------------
// Fused prologue: all 5 weight conversions + SiLU in ONE launch.
// float4 granularity; segment dispatch by global index.
// ---------------------------------------------------------------------------
#define P_S0 (NTOK * ADIM / 4)
#define P_S1 (P_S0 + QKVC * DIMd / 4)
#define P_S2 (P_S1 + DIMd * DIMd / 4)
#define P_S3 (P_S2 + MLPD * DIMd / 4)
#define P_S4 (P_S3 + DIMd * MLPD / 4)
#define P_S5 (P_S4 + MODC * ADIM / 4)

__global__ void prep_kernel(
    const float* __restrict__ aemb, const float* __restrict__ Wqkv,
    const float* __restrict__ Wout, const float* __restrict__ W1,
    const float* __restrict__ W2,   const float* __restrict__ Wmod,
    bf16* __restrict__ silu_o, bf16* __restrict__ wqkv_o,
    bf16* __restrict__ wout_o, bf16* __restrict__ w1_o,
    bf16* __restrict__ w2_o,   bf16* __restrict__ wmod_o)
{
    int i = blockIdx.x * blockDim.x + threadIdx.x;
    const float* src; bf16* dst; int base; bool is_silu = false;
    if      (i < P_S0) { src = aemb; dst = silu_o; base = i;        is_silu = true; }
    else if (i < P_S1) { src = Wqkv; dst = wqkv_o; base = i - P_S0; }
    else if (i < P_S2) { src = Wout; dst = wout_o; base = i - P_S1; }
    else if (i < P_S3) { src = W1;   dst = w1_o;   base = i - P_S2; }
    else if (i < P_S4) { src = W2;   dst = w2_o;   base = i - P_S3; }
    else if (i < P_S5) { src = Wmod; dst = wmod_o; base = i - P_S4; }
    else return;
    float4 v = ((const float4*)src)[base];
    if (is_silu) {
        v.x = v.x / (1.0f + __expf(-v.x));
        v.y = v.y / (1.0f + __expf(-v.y));
        v.z = v.z / (1.0f + __expf(-v.z));
        v.w = v.w / (1.0f + __expf(-v.w));
    }
    uint2 o;
    o.x = pack_bf2(v.x, v.y);
    o.y = pack_bf2(v.z, v.w);
    ((uint2*)dst)[base] = o;
}

// ---------------------------------------------------------------------------
// Fused LayerNorm + AdaLN modulation -> bf16
// ---------------------------------------------------------------------------
__global__ void lnmod_kernel(const float* __restrict__ x,
                             const bf16* __restrict__ mod,
                             int shift_off, int scale_off,
                             bf16* __restrict__ out)
{
    int row = blockIdx.x;
    int t   = threadIdx.x;
    const float* xr = x + (size_t)row * DIMd;

    float v[4];
    float s1 = 0.f, s2 = 0.f;
#pragma unroll
    for (int j = 0; j < 4; j++) {
        float z = xr[t + j * 128];
        v[j] = z; s1 += z; s2 += z * z;
    }
#pragma unroll
    for (int off = 16; off; off >>= 1) {
        s1 += __shfl_xor_sync(0xffffffffu, s1, off);
        s2 += __shfl_xor_sync(0xffffffffu, s2, off);
    }
    __shared__ float r1[4], r2[4];
    int w = t >> 5;
    if ((t & 31) == 0) { r1[w] = s1; r2[w] = s2; }
    __syncthreads();
    s1 = r1[0] + r1[1] + r1[2] + r1[3];
    s2 = r2[0] + r2[1] + r2[2] + r2[3];

    float mu   = s1 * (1.0f / DIMd);
    float var  = s2 * (1.0f / DIMd) - mu * mu;
    float rstd = rsqrtf(var + 1e-5f);

    const bf16* mrow = mod + (size_t)row * MODC;
    bf16* orow = out + (size_t)row * DIMd;
#pragma unroll
    for (int j = 0; j < 4; j++) {
        int c = t + j * 128;
        float sc = __bfloat162float(mrow[scale_off + c]);
        float sh = __bfloat162float(mrow[shift_off + c]);
        orow[c] = __float2bfloat16((v[j] - mu) * rstd * (1.0f + sc) + sh);
    }
}

// ---------------------------------------------------------------------------
// bf16 tensor-core GEMM: 128x128x32 tiles, 4-stage cp.async pipeline,
// one __syncthreads per tile, register double-buffered fragments.
// EPI: 1 = GELU(acc+bias) bf16, 2 = res + gate*(acc+bias) fp32, 3 = acc(+bias) bf16
// ---------------------------------------------------------------------------
#define GBM 128
#define GBN 128
#define GBK 32
#define GSTR (GBK + 8)
#define STAGES 4
#define STAGE_ELEMS (2 * GBM * GSTR)
#define GEMM_SMEM (STAGES * STAGE_ELEMS * 2)   // 81920 B

__device__ __forceinline__ void g2s_tile(
    const bf16* __restrict__ Ag, const bf16* __restrict__ Bg,
    int K, int kt, bf16* smemBuf, int lr, int lc)
{
    bf16* As = smemBuf + (kt % STAGES) * STAGE_ELEMS;
    bf16* Bs = As + GBM * GSTR;
    const int k0 = kt * GBK;
#pragma unroll
    for (int p = 0; p < 2; p++) {
        int row = lr + p * 64;
        unsigned sA = smem_u32(&As[row * GSTR + lc]);
        asm volatile("cp.async.cg.shared.global [%0], [%1], 16;\n"
                     :: "r"(sA), "l"(Ag + (size_t)row * K + k0 + lc));
        unsigned sB = smem_u32(&Bs[row * GSTR + lc]);
        asm volatile("cp.async.cg.shared.global [%0], [%1], 16;\n"
                     :: "r"(sB), "l"(Bg + (size_t)row * K + k0 + lc));
    }
    asm volatile("cp.async.commit_group;\n" ::: "memory");
}

__device__ __forceinline__ void load_frags(
    const bf16* As, const bf16* Bs, int ks, int wm, int wn, int lane,
    unsigned aF[4][4], unsigned bF[4][2])
{
    const int kk = ks * 16;
#pragma unroll
    for (int i = 0; i < 4; i++) {
        int row = wm * 64 + i * 16 + (lane & 15);
        int col = kk + (lane >> 4) * 8;
        unsigned addr = smem_u32(&As[row * GSTR + col]);
        asm volatile(
            "ldmatrix.sync.aligned.m8n8.x4.shared.b16 {%0,%1,%2,%3}, [%4];\n"
            : "=r"(aF[i][0]), "=r"(aF[i][1]), "=r"(aF[i][2]), "=r"(aF[i][3])
            : "r"(addr));
    }
#pragma unroll
    for (int j = 0; j < 2; j++) {
        int row = wn * 32 + j * 16 + (lane >> 4) * 8 + (lane & 7);
        int col = kk + ((lane >> 3) & 1) * 8;
        unsigned addr = smem_u32(&Bs[row * GSTR + col]);
        unsigned r0, r1, r2, r3;
        asm volatile(
            "ldmatrix.sync.aligned.m8n8.x4.shared.b16 {%0,%1,%2,%3}, [%4];\n"
            : "=r"(r0), "=r"(r1), "=r"(r2), "=r"(r3)
            : "r"(addr));
        bF[2 * j + 0][0] = r0; bF[2 * j + 0][1] = r1;
        bF[2 * j + 1][0] = r2; bF[2 * j + 1][1] = r3;
    }
}

template <int EPI>
__global__ void __launch_bounds__(256) mma_gemm(
    const bf16* __restrict__ A,
    const bf16* __restrict__ Bw,
    const float* __restrict__ bias,
    const float* __restrict__ res,
    const bf16* __restrict__ gate, int gate_off,
    void* __restrict__ Cout,
    int M, int N, int K)
{
    extern __shared__ bf16 smemBuf[];

    const int tid  = threadIdx.x;
    const int bx   = blockIdx.x, by = blockIdx.y;
    const int wid  = tid >> 5, lane = tid & 31;
    const int wm   = wid & 1;
    const int wn   = wid >> 1;

    const int lr = tid >> 2;
    const int lc = (tid & 3) * 8;
    const bf16* Ag = A  + (size_t)(by * GBM) * K;
    const bf16* Bg = Bw + (size_t)(bx * GBN) * K;

    float acc[4][4][4];
#pragma unroll
    for (int i = 0; i < 4; i++)
#pragma unroll
        for (int j = 0; j < 4; j++)
#pragma unroll
            for (int r = 0; r < 4; r++) acc[i][j][r] = 0.f;

    const int KT = K / GBK;

    g2s_tile(Ag, Bg, K, 0, smemBuf, lr, lc);
    g2s_tile(Ag, Bg, K, 1, smemBuf, lr, lc);
    g2s_tile(Ag, Bg, K, 2, smemBuf, lr, lc);

    for (int kt = 0; kt < KT; kt++) {
        // allowed pending groups = min(2, KT-1-kt)
        if (kt + 1 >= KT)
            asm volatile("cp.async.wait_group 0;" ::: "memory");
        else if (kt + 2 >= KT)
            asm volatile("cp.async.wait_group 1;" ::: "memory");
        else
            asm volatile("cp.async.wait_group 2;" ::: "memory");
        __syncthreads();

        if (kt + 3 < KT) g2s_tile(Ag, Bg, K, kt + 3, smemBuf, lr, lc);

        const bf16* As = smemBuf + (kt % STAGES) * STAGE_ELEMS;
        const bf16* Bs = As + GBM * GSTR;

        unsigned aF[2][4][4], bF[2][4][2];
        load_frags(As, Bs, 0, wm, wn, lane, aF[0], bF[0]);

#pragma unroll
        for (int ks = 0; ks < 2; ks++) {
            if (ks == 0) load_frags(As, Bs, 1, wm, wn, lane, aF[1], bF[1]);
#pragma unroll
            for (int i = 0; i < 4; i++)
#pragma unroll
                for (int j = 0; j < 4; j++) {
                    asm volatile(
                        "mma.sync.aligned.m16n8k16.row.col.f32.bf16.bf16.f32 "
                        "{%0,%1,%2,%3}, {%4,%5,%6,%7}, {%8,%9}, {%0,%1,%2,%3};\n"
                        : "+f"(acc[i][j][0]), "+f"(acc[i][j][1]),
                          "+f"(acc[i][j][2]), "+f"(acc[i][j][3])
                        : "r"(aF[ks][i][0]), "r"(aF[ks][i][1]),
                          "r"(aF[ks][i][2]), "r"(aF[ks][i][3]),
                          "r"(bF[ks][j][0]), "r"(bF[ks][j][1]));
                }
        }
    }

    const int grp = lane >> 2;
    const int qd  = (lane & 3) * 2;
#pragma unroll
    for (int i = 0; i < 4; i++) {
#pragma unroll
        for (int half = 0; half < 2; half++) {
            int m = by * GBM + wm * 64 + i * 16 + grp + half * 8;
            size_t crow = (size_t)m * N;
            size_t grow = (size_t)m * MODC + gate_off;
#pragma unroll
            for (int j = 0; j < 4; j++) {
                int n = bx * GBN + wn * 32 + j * 8 + qd;
                float v0 = acc[i][j][half * 2 + 0];
                float v1 = acc[i][j][half * 2 + 1];
                if (bias) { v0 += bias[n]; v1 += bias[n + 1]; }
                if (EPI == 1) { v0 = gelu_exact(v0); v1 = gelu_exact(v1); }
                if (EPI == 1 || EPI == 3) {
                    bf16* C = (bf16*)Cout;
                    *(unsigned*)(C + crow + n) = pack_bf2(v0, v1);
                } else if (EPI == 2) {
                    float* C = (float*)Cout;
                    float g0 = __bfloat162float(gate[grow + n]);
                    float g1 = __bfloat162float(gate[grow + n + 1]);
                    C[crow + n]     = res[crow + n]     + g0 * v0;
                    C[crow + n + 1] = res[crow + n + 1] + g1 * v1;
                }
            }
        }
    }
}

// ---------------------------------------------------------------------------
// Tensor-core causal flash attention, 3-stage cp.async K/V pipeline.
// CTA = 128 queries of one (b,h); 4 warps; 64-key tiles; one sync per tile.
// Q staged through stage-0/1 smem before the loop.
// ---------------------------------------------------------------------------
#define ASTR 72
#define KVTILE (64 * ASTR)
#define ATTN_SMEM (3 * 2 * KVTILE * 2)    // 55296 B dynamic

__device__ __forceinline__ void attn_prefetch(
    const bf16* __restrict__ qkv, bf16* pool, int b, int h, int kt, int tid)
{
    bf16* Ks = pool + (kt % 3) * 2 * KVTILE;
    bf16* Vs = Ks + KVTILE;
    const int k0 = kt * 64;
#pragma unroll
    for (int it = 0; it < 4; it++) {
        int idx = tid + it * 128;
        int row = idx >> 3, c8 = (idx & 7) * 8;
        const bf16* src = qkv + (size_t)(b * Tt + k0 + row) * QKVC + h * 64 + c8;
        asm volatile("cp.async.cg.shared.global [%0], [%1], 16;\n"
                     :: "r"(smem_u32(&Ks[row * ASTR + c8])), "l"(src + 512));
        asm volatile("cp.async.cg.shared.global [%0], [%1], 16;\n"
                     :: "r"(smem_u32(&Vs[row * ASTR + c8])), "l"(src + 1024));
    }
    asm volatile("cp.async.commit_group;\n" ::: "memory");
}

__global__ void __launch_bounds__(128) attn_tc_kernel(
    const bf16* __restrict__ qkv, bf16* __restrict__ out)
{
    extern __shared__ bf16 pool[];
    const int b  = blockIdx.z, h = blockIdx.y, qt = blockIdx.x;
    const int tid = threadIdx.x, w = tid >> 5, lane = tid & 31;

    // Stage Q (128 x 64) into stage-0/1 area (contiguous 128*ASTR)
#pragma unroll
    for (int it = 0; it < 8; it++) {
        int idx = tid + it * 128;
        int row = idx >> 3, c8 = (idx & 7) * 8;
        const bf16* src =
            qkv + (size_t)(b * Tt + qt * 128 + row) * QKVC + h * 64 + c8;
        asm volatile("cp.async.cg.shared.global [%0], [%1], 16;\n"
                     :: "r"(smem_u32(&pool[row * ASTR + c8])), "l"(src));
    }
    asm volatile("cp.async.commit_group;\n" ::: "memory");
    asm volatile("cp.async.wait_group 0;" ::: "memory");
    __syncthreads();

    unsigned qF[2][4][4];
#pragma unroll
    for (int i = 0; i < 2; i++)
#pragma unroll
        for (int kk = 0; kk < 4; kk++) {
            int row = w * 32 + i * 16 + (lane & 15);
            int col = kk * 16 + (lane >> 4) * 8;
            unsigned addr = smem_u32(&pool[row * ASTR + col]);
            asm volatile(
                "ldmatrix.sync.aligned.m8n8.x4.shared.b16 {%0,%1,%2,%3}, [%4];\n"
                : "=r"(qF[i][kk][0]), "=r"(qF[i][kk][1]),
                  "=r"(qF[i][kk][2]), "=r"(qF[i][kk][3])
                : "r"(addr));
        }
    __syncthreads();   // all warps done reading Q before stage 0/1 refilled

    float oAcc[2][8][4];
#pragma unroll
    for (int i = 0; i < 2; i++)
#pragma unroll
        for (int j = 0; j < 8; j++)
#pragma unroll
            for (int r = 0; r < 4; r++) oAcc[i][j][r] = 0.f;
    float lsum[2][2] = {{0.f, 0.f}, {0.f, 0.f}};

    const int qmax  = qt * 128 + w * 32 + 31;
    const int ntile = 2 * (qt + 1);

    attn_prefetch(qkv, pool, b, h, 0, tid);
    if (ntile > 1) attn_prefetch(qkv, pool, b, h, 1, tid);

    for (int kt = 0; kt < ntile; kt++) {
        if (kt + 1 >= ntile)
            asm volatile("cp.async.wait_group 0;" ::: "memory");
        else
            asm volatile("cp.async.wait_group 1;" ::: "memory");
        __syncthreads();

        if (kt + 2 < ntile) attn_prefetch(qkv, pool, b, h, kt + 2, tid);

        const bf16* Ks = pool + (kt % 3) * 2 * KVTILE;
        const bf16* Vs = Ks + KVTILE;
        const int k0 = kt * 64;

        if (k0 <= qmax) {
            float sAcc[2][8][4];
#pragma unroll
            for (int i = 0; i < 2; i++)
#pragma unroll
                for (int j = 0; j < 8; j++)
#pragma unroll
                    for (int r = 0; r < 4; r++) sAcc[i][j][r] = 0.f;

#pragma unroll
            for (int kk = 0; kk < 4; kk++) {
#pragma unroll
                for (int j2 = 0; j2 < 4; j2++) {
                    int row = j2 * 16 + (lane >> 4) * 8 + (lane & 7);
                    int col = kk * 16 + ((lane >> 3) & 1) * 8;
                    unsigned addr = smem_u32(&Ks[row * ASTR + col]);
                    unsigned r0, r1, r2, r3;
                    asm volatile(
                        "ldmatrix.sync.aligned.m8n8.x4.shared.b16 {%0,%1,%2,%3}, [%4];\n"
                        : "=r"(r0), "=r"(r1), "=r"(r2), "=r"(r3) : "r"(addr));
#pragma unroll
                    for (int i = 0; i < 2; i++) {
                        asm volatile(
                            "mma.sync.aligned.m16n8k16.row.col.f32.bf16.bf16.f32 "
                            "{%0,%1,%2,%3}, {%4,%5,%6,%7}, {%8,%9}, {%0,%1,%2,%3};\n"
                            : "+f"(sAcc[i][2*j2][0]), "+f"(sAcc[i][2*j2][1]),
                              "+f"(sAcc[i][2*j2][2]), "+f"(sAcc[i][2*j2][3])
                            : "r"(qF[i][kk][0]), "r"(qF[i][kk][1]),
                              "r"(qF[i][kk][2]), "r"(qF[i][kk][3]),
                              "r"(r0), "r"(r1));
                        asm volatile(
                            "mma.sync.aligned.m16n8k16.row.col.f32.bf16.bf16.f32 "
                            "{%0,%1,%2,%3}, {%4,%5,%6,%7}, {%8,%9}, {%0,%1,%2,%3};\n"
                            : "+f"(sAcc[i][2*j2+1][0]), "+f"(sAcc[i][2*j2+1][1]),
                              "+f"(sAcc[i][2*j2+1][2]), "+f"(sAcc[i][2*j2+1][3])
                            : "r"(qF[i][kk][0]), "r"(qF[i][kk][1]),
                              "r"(qF[i][kk][2]), "r"(qF[i][kk][3]),
                              "r"(r2), "r"(r3));
                    }
                }
            }

            const int qrow0 = qt * 128 + w * 32 + (lane >> 2);
#pragma unroll
            for (int i = 0; i < 2; i++) {
                int q0 = qrow0 + i * 16;
                int q1 = q0 + 8;
#pragma unroll
                for (int j = 0; j < 8; j++) {
                    int kc = k0 + j * 8 + (lane & 3) * 2;
                    float p0 = (kc     <= q0) ? fast_exp(sAcc[i][j][0] * 0.125f) : 0.f;
                    float p1 = (kc + 1 <= q0) ? fast_exp(sAcc[i][j][1] * 0.125f) : 0.f;
                    float p2 = (kc     <= q1) ? fast_exp(sAcc[i][j][2] * 0.125f) : 0.f;
                    float p3 = (kc + 1 <= q1) ? fast_exp(sAcc[i][j][3] * 0.125f) : 0.f;
                    sAcc[i][j][0] = p0; sAcc[i][j][1] = p1;
                    sAcc[i][j][2] = p2; sAcc[i][j][3] = p3;
                    lsum[i][0] += p0 + p1;
                    lsum[i][1] += p2 + p3;
                }
            }

#pragma unroll
            for (int c = 0; c < 4; c++) {
                unsigned pF[2][4];
#pragma unroll
                for (int i = 0; i < 2; i++) {
                    pF[i][0] = pack_bf2(sAcc[i][2*c  ][0], sAcc[i][2*c  ][1]);
                    pF[i][1] = pack_bf2(sAcc[i][2*c  ][2], sAcc[i][2*c  ][3]);
                    pF[i][2] = pack_bf2(sAcc[i][2*c+1][0], sAcc[i][2*c+1][1]);
                    pF[i][3] = pack_bf2(sAcc[i][2*c+1][2], sAcc[i][2*c+1][3]);
                }
#pragma unroll
                for (int d2 = 0; d2 < 4; d2++) {
                    int g = lane >> 3;
                    int row = c * 16 + (g & 1) * 8 + (lane & 7);
                    int col = d2 * 16 + (g >> 1) * 8;
                    unsigned addr = smem_u32(&Vs[row * ASTR + col]);
                    unsigned v0, v1, v2, v3;
                    asm volatile(
                        "ldmatrix.sync.aligned.m8n8.x4.trans.shared.b16 {%0,%1,%2,%3}, [%4];\n"
                        : "=r"(v0), "=r"(v1), "=r"(v2), "=r"(v3) : "r"(addr));
#pragma unroll
                    for (int i = 0; i < 2; i++) {
                        asm volatile(
                            "mma.sync.aligned.m16n8k16.row.col.f32.bf16.bf16.f32 "
                            "{%0,%1,%2,%3}, {%4,%5,%6,%7}, {%8,%9}, {%0,%1,%2,%3};\n"
                            : "+f"(oAcc[i][2*d2][0]), "+f"(oAcc[i][2*d2][1]),
                              "+f"(oAcc[i][2*d2][2]), "+f"(oAcc[i][2*d2][3])
                            : "r"(pF[i][0]), "r"(pF[i][1]), "r"(pF[i][2]), "r"(pF[i][3]),
                              "r"(v0), "r"(v1));
                        asm volatile(
                            "mma.sync.aligned.m16n8k16.row.col.f32.bf16.bf16.f32 "
                            "{%0,%1,%2,%3}, {%4,%5,%6,%7}, {%8,%9}, {%0,%1,%2,%3};\n"
                            : "+f"(oAcc[i][2*d2+1][0]), "+f"(oAcc[i][2*d2+1][1]),
                              "+f"(oAcc[i][2*d2+1][2]), "+f"(oAcc[i][2*d2+1][3])
                            : "r"(pF[i][0]), "r"(pF[i][1]), "r"(pF[i][2]), "r"(pF[i][3]),
                              "r"(v2), "r"(v3));
                    }
                }
            }
        }
    }

#pragma unroll
    for (int i = 0; i < 2; i++) {
#pragma unroll
        for (int hf = 0; hf < 2; hf++) {
            float l = lsum[i][hf];
            l += __shfl_xor_sync(0xffffffffu, l, 1);
            l += __shfl_xor_sync(0xffffffffu, l, 2);
            float inv = 1.0f / l;
            int qg = qt * 128 + w * 32 + i * 16 + (lane >> 2) + hf * 8;
            bf16* orow = out + (size_t)(b * Tt + qg) * DIMd + h * DHEAD;
#pragma unroll
            for (int j = 0; j < 8; j++) {
                int d = j * 8 + (lane & 3) * 2;
                *(unsigned*)(orow + d) =
                    pack_bf2(oAcc[i][j][hf * 2] * inv, oAcc[i][j][hf * 2 + 1] * inv);
            }
        }
    }
}

// ---------------------------------------------------------------------------
// Launch
// Inputs: 0:x 1:action_emb 2:causal_mask 3:Wqkv 4:Wout 5:bout
//         6:W1 7:b1 8:W2 9:b2 10:Wmod 11:bmod
// ---------------------------------------------------------------------------
extern "C" void kernel_launch(void* const* d_in, const int* in_sizes, int n_in,
                              void* d_out, int out_size)
{
    const float* x    = (const float*)d_in[0];
    const float* aemb = (const float*)d_in[1];
    const float* Wqkv = (const float*)d_in[3];
    const float* Wout = (const float*)d_in[4];
    const float* bout = (const float*)d_in[5];
    const float* W1   = (const float*)d_in[6];
    const float* b1   = (const float*)d_in[7];
    const float* W2   = (const float*)d_in[8];
    const float* b2   = (const float*)d_in[9];
    const float* Wmod = (const float*)d_in[10];
    const float* bmod = (const float*)d_in[11];
    float* out = (float*)d_out;

    float *x1_p;
    bf16 *mod_p, *silu_p, *h_p, *qkv_p, *attn_p, *mlp_p;
    bf16 *wqkv_p, *wout_p, *w1_p, *w2_p, *wmod_p;
    cudaGetSymbolAddress((void**)&x1_p,   g_x1);
    cudaGetSymbolAddress((void**)&mod_p,  g_mod_bf);
    cudaGetSymbolAddress((void**)&silu_p, g_silu_bf);
    cudaGetSymbolAddress((void**)&h_p,    g_h_bf);
    cudaGetSymbolAddress((void**)&qkv_p,  g_qkv_bf);
    cudaGetSymbolAddress((void**)&attn_p, g_attn_bf);
    cudaGetSymbolAddress((void**)&mlp_p,  g_mlp_bf);
    cudaGetSymbolAddress((void**)&wqkv_p, g_Wqkv_bf);
    cudaGetSymbolAddress((void**)&wout_p, g_Wout_bf);
    cudaGetSymbolAddress((void**)&w1_p,   g_W1_bf);
    cudaGetSymbolAddress((void**)&w2_p,   g_W2_bf);
    cudaGetSymbolAddress((void**)&wmod_p, g_Wmod_bf);

    cudaFuncSetAttribute(mma_gemm<1>, cudaFuncAttributeMaxDynamicSharedMemorySize, GEMM_SMEM);
    cudaFuncSetAttribute(mma_gemm<2>, cudaFuncAttributeMaxDynamicSharedMemorySize, GEMM_SMEM);
    cudaFuncSetAttribute(mma_gemm<3>, cudaFuncAttributeMaxDynamicSharedMemorySize, GEMM_SMEM);
    cudaFuncSetAttribute(attn_tc_kernel, cudaFuncAttributeMaxDynamicSharedMemorySize, ATTN_SMEM);

    // 1) fused prologue: weight conversions + silu (one launch)
    prep_kernel<<<(P_S5 + 255) / 256, 256>>>(
        aemb, Wqkv, Wout, W1, W2, Wmod,
        silu_p, wqkv_p, wout_p, w1_p, w2_p, wmod_p);

    // 2) mod = silu_a @ Wmod^T + bmod -> bf16
    mma_gemm<3><<<dim3(MODC / GBN, NTOK / GBM), 256, GEMM_SMEM>>>(
        silu_p, wmod_p, bmod, nullptr, nullptr, 0, mod_p, NTOK, MODC, ADIM);

    // 3) h = LN(x)*(1+scale1)+shift1 -> bf16
    lnmod_kernel<<<NTOK, 128>>>(x, mod_p, 0, DIMd, h_p);

    // 4) qkv = h @ Wqkv^T -> bf16
    mma_gemm<3><<<dim3(QKVC / GBN, NTOK / GBM), 256, GEMM_SMEM>>>(
        h_p, wqkv_p, nullptr, nullptr, nullptr, 0, qkv_p, NTOK, QKVC, DIMd);

    // 5) tensor-core causal attention -> bf16
    attn_tc_kernel<<<dim3(Tt / 128, NHEAD, Bb), 128, ATTN_SMEM>>>(qkv_p, attn_p);

    // 6) x1 = x + gate1 * (attn @ Wout^T + bout)  fp32 out
    mma_gemm<2><<<dim3(DIMd / GBN, NTOK / GBM), 256, GEMM_SMEM>>>(
        attn_p, wout_p, bout, x, mod_p, 2 * DIMd, x1_p, NTOK, DIMd, DIMd);

    // 7) h = LN(x1)*(1+scale2)+shift2 -> bf16
    lnmod_kernel<<<NTOK, 128>>>(x1_p, mod_p, 3 * DIMd, 4 * DIMd, h_p);

    // 8) mlp = gelu(h @ W1^T + b1) -> bf16
    mma_gemm<1><<<dim3(MLPD / GBN, NTOK / GBM), 256, GEMM_SMEM>>>(
        h_p, w1_p, b1, nullptr, nullptr, 0, mlp_p, NTOK, MLPD, DIMd);

    // 9) out = x1 + gate2 * (mlp @ W2^T + b2)  fp32 out
    mma_gemm<1 + 1><<<dim3(DIMd / GBN, NTOK / GBM), 256, GEMM_SMEM>>>(
        mlp_p, w2_p, b2, x1_p, mod_p, 5 * DIMd, out, NTOK, DIMd, MLPD);
}